// round 3
// baseline (speedup 1.0000x reference)
#include <cuda_runtime.h>
#include <math.h>

#define HEADS   4
#define HD      32
#define NTOK    256
#define NWIN    512
#define POSN    961
#define QKSCALE 0.17677669529663689f  // 32^-0.5

// ---------------- scratch ----------------
__device__ float g_q[NWIN * HEADS * NTOK * HD];
__device__ float g_k[NWIN * HEADS * NTOK * HD];
__device__ float g_v[NWIN * HEADS * NTOK * HD];
__device__ float g_wT[128 * 384];
__device__ float g_cs[384];
__device__ float g_cb[384];
__device__ float g_pos[HEADS * POSN];

// ---------------- f32x2 helpers ----------------
typedef unsigned long long u64;
__device__ __forceinline__ u64 pk2(float x, float y) {
    u64 r; asm("mov.b64 %0,{%1,%2};" : "=l"(r) : "f"(x), "f"(y)); return r;
}
__device__ __forceinline__ u64 pk2u(unsigned x, unsigned y) {
    u64 r; asm("mov.b64 %0,{%1,%2};" : "=l"(r) : "r"(x), "r"(y)); return r;
}
__device__ __forceinline__ void fma2(u64& d, u64 a, u64 b) {
    asm("fma.rn.f32x2 %0,%1,%2,%0;" : "+l"(d) : "l"(a), "l"(b));
}
__device__ __forceinline__ float2 up2(u64 v) {
    float lo, hi; asm("mov.b64 {%0,%1},%2;" : "=f"(lo), "=f"(hi) : "l"(v));
    float2 f; f.x = lo; f.y = hi; return f;
}
__device__ __forceinline__ unsigned bf2pack(float lo, float hi) {
    unsigned r; asm("cvt.rn.bf16x2.f32 %0,%1,%2;" : "=r"(r) : "f"(hi), "f"(lo)); return r;
}

// ---------------- pos-bias MLP ----------------
__device__ __forceinline__ void ln_relu8(float* a, const float* g, const float* b) {
    float m = 0.f;
#pragma unroll
    for (int u = 0; u < 8; u++) m += a[u];
    m *= 0.125f;
    float v = 0.f;
#pragma unroll
    for (int u = 0; u < 8; u++) { float d = a[u] - m; v += d * d; }
    v *= 0.125f;
    float r = rsqrtf(v + 1e-5f);
#pragma unroll
    for (int u = 0; u < 8; u++) a[u] = fmaxf((a[u] - m) * r * g[u] + b[u], 0.f);
}

__device__ __forceinline__ void fc8(const float* a, float* y, const float* w, const float* b) {
#pragma unroll
    for (int o = 0; o < 8; o++) {
        float s = b[o];
#pragma unroll
        for (int u = 0; u < 8; u++) s += a[u] * w[o * 8 + u];
        y[o] = s;
    }
}

__global__ void prep_pos_kernel(
    const float* __restrict__ pp_w, const float* __restrict__ pp_b,
    const float* __restrict__ l1_g, const float* __restrict__ l1_b,
    const float* __restrict__ f1_w, const float* __restrict__ f1_b,
    const float* __restrict__ l2_g, const float* __restrict__ l2_b,
    const float* __restrict__ f2_w, const float* __restrict__ f2_b,
    const float* __restrict__ l3_g, const float* __restrict__ l3_b,
    const float* __restrict__ f3_w, const float* __restrict__ f3_b)
{
    int p = blockIdx.x * blockDim.x + threadIdx.x;
    if (p >= POSN) return;
    float bh = (float)(p / 31 - 15);
    float bw = (float)(p % 31 - 15);
    float a[8], y[8];
#pragma unroll
    for (int u = 0; u < 8; u++) a[u] = bh * pp_w[2 * u] + bw * pp_w[2 * u + 1] + pp_b[u];
    ln_relu8(a, l1_g, l1_b);
    fc8(a, y, f1_w, f1_b);
    ln_relu8(y, l2_g, l2_b);
    fc8(y, a, f2_w, f2_b);
    ln_relu8(a, l3_g, l3_b);
#pragma unroll
    for (int hh = 0; hh < HEADS; hh++) {
        float s = f3_b[hh];
#pragma unroll
        for (int u = 0; u < 8; u++) s += a[u] * f3_w[hh * 8 + u];
        g_pos[hh * POSN + p] = s;
    }
}

// ---------------- fold LN gamma into QKV weight ----------------
__global__ void prep_w_kernel(const float* __restrict__ qkv_w, const float* __restrict__ qkv_b,
                              const float* __restrict__ g1, const float* __restrict__ b1)
{
    __shared__ float s1[128], s2[128];
    int j = blockIdx.x;
    int k = threadIdx.x;
    float w = qkv_w[j * 128 + k];
    float wg = w * g1[k];
    g_wT[k * 384 + j] = wg;
    s1[k] = wg;
    s2[k] = w * b1[k];
    __syncthreads();
    for (int o = 64; o > 0; o >>= 1) {
        if (k < o) { s1[k] += s1[k + o]; s2[k] += s2[k + o]; }
        __syncthreads();
    }
    if (k == 0) { g_cs[j] = s1[0]; g_cb[j] = s2[0] + qkv_b[j]; }
}

// ---------------- fused LN + QKV GEMM (512 threads, f32x2) ----------------
#define QK_PADA 132
#define QKV_SMEM_FLOATS (64 * QK_PADA + 64 * 384 + 64 + 64)

__global__ __launch_bounds__(512, 1) void qkv_kernel(const float* __restrict__ x)
{
    extern __shared__ float sm[];
    float* As    = sm;                         // [64][132]
    float* Bs    = sm + 64 * QK_PADA;          // [64][384]
    float* smean = Bs + 64 * 384;
    float* srstd = smean + 64;

    int tid = threadIdx.x;
    int t0 = blockIdx.x * 64;

#pragma unroll
    for (int i = 0; i < 4; i++) {
        int f = i * 512 + tid;                 // 2048 float4
        int m = f >> 5, c4 = f & 31;
        int t = t0 + m;
        int w = t >> 8, n = t & 255;
        int row = ((w >> 8) << 16) + (((((w >> 4) & 15) << 4) + (n >> 4)) << 8)
                + ((w & 15) << 4) + (n & 15);
        *(float4*)(As + m * QK_PADA + c4 * 4) =
            *(const float4*)(x + (size_t)row * 128 + c4 * 4);
    }
    __syncthreads();

    int wy = tid >> 5, tx = tid & 31;

    // per-row LN stats: warp wy handles rows wy*4..+4
    for (int rr = 0; rr < 4; rr++) {
        int m = wy * 4 + rr;
        float s = 0.f, q = 0.f;
#pragma unroll
        for (int c = 0; c < 4; c++) {
            float v = As[m * QK_PADA + tx + 32 * c];
            s += v; q += v * v;
        }
#pragma unroll
        for (int o = 16; o; o >>= 1) {
            s += __shfl_xor_sync(0xffffffffu, s, o);
            q += __shfl_xor_sync(0xffffffffu, q, o);
        }
        if (tx == 0) {
            float mu = s * (1.f / 128.f);
            smean[m] = mu;
            srstd[m] = rsqrtf(q * (1.f / 128.f) - mu * mu + 1e-5f);
        }
    }

    u64 acc[2][12];
#pragma unroll
    for (int p = 0; p < 2; p++)
#pragma unroll
        for (int u = 0; u < 12; u++) acc[p][u] = 0ull;

    for (int kt = 0; kt < 2; kt++) {
        __syncthreads();
#pragma unroll
        for (int i = 0; i < 12; i++) {
            int f = i * 512 + tid;             // 6144 float4
            int kk = f / 96, c4 = f % 96;
            *(float4*)(Bs + kk * 384 + c4 * 4) =
                *(const float4*)(g_wT + (size_t)(kt * 64 + kk) * 384 + c4 * 4);
        }
        __syncthreads();
#pragma unroll 2
        for (int kk = 0; kk < 64; kk++) {
            const float* arow = As + (wy * 4) * QK_PADA + kt * 64 + kk;
            u64 qa[2];
            qa[0] = pk2(arow[0], arow[QK_PADA]);
            qa[1] = pk2(arow[2 * QK_PADA], arow[3 * QK_PADA]);
            const float* brow = Bs + kk * 384 + tx;
#pragma unroll
            for (int u = 0; u < 12; u++) {
                float bb = brow[32 * u];
                u64 b2 = pk2(bb, bb);
                fma2(acc[0][u], qa[0], b2);
                fma2(acc[1][u], qa[1], b2);
            }
        }
    }
    __syncthreads();

#pragma unroll
    for (int u = 0; u < 12; u++) {
        int j = tx + 32 * u;
        float cs = g_cs[j], cb = g_cb[j];
        int head = u & 3;
        float* dst = (u < 4) ? g_q : (u < 8) ? g_k : g_v;
#pragma unroll
        for (int p = 0; p < 2; p++) {
            float2 v = up2(acc[p][u]);
#pragma unroll
            for (int e = 0; e < 2; e++) {
                int m = wy * 4 + 2 * p + e;
                int t = t0 + m;
                int w = t >> 8, n = t & 255;
                float val = srstd[m] * (((e == 0) ? v.x : v.y) - smean[m] * cs) + cb;
                if (u < 4) val *= QKSCALE;
                dst[((size_t)(w * 4 + head) * 256 + n) * 32 + tx] = val;
            }
        }
    }
}

// ---------------- attention: 512 threads per (window, head) ----------------
#define KST 260
#define PSTU 68        // u32 stride for bf16x2 P
#define RST 33
// floats: ks 8320 + qs 8320 + vs 8192 + Ps 17408 + posh 964
#define ATTN_SMEM_FLOATS (32*KST*2 + 256*32 + 256*PSTU + 964)

__global__ __launch_bounds__(512, 1) void attn_kernel(const float* __restrict__ x,
                                                      float* __restrict__ out)
{
    extern __shared__ float sm[];
    float*    ks   = sm;                       // [32][260] k d-major
    float*    qs   = ks + 32 * KST;            // [32][260] q d-major
    float*    vs   = qs + 32 * KST;            // [256][32]
    unsigned* Psu  = (unsigned*)(vs + 256 * 32);  // [256][68] bf16x2 P^T (swizzled)
    float*    redf = (float*)Psu;              // alias: [4][128][33] k-split partials
    float*    posh = (float*)(Psu + 256 * PSTU);  // [961]+pad

    int tid = threadIdx.x;
    int wy = tid >> 5, tx = tid & 31;
    int w = blockIdx.x >> 2, h = blockIdx.x & 3;
    size_t base = (size_t)(w * 4 + h) * 256 * 32;

    for (int p = tid; p < POSN; p += 512) posh[p] = g_pos[h * POSN + p];

    // v straight copy
#pragma unroll
    for (int i = 0; i < 4; i++) {
        int f = i * 512 + tid;
        int n = f >> 3, d4 = f & 7;
        *(float4*)(vs + n * 32 + d4 * 4) = *(const float4*)(g_v + base + n * 32 + d4 * 4);
    }

    // k,q transposed to d-major: warps 0-7 -> ks, warps 8-15 -> qs
    {
        const float* src = (wy < 8) ? (g_k + base) : (g_q + base);
        float* dst = (wy < 8) ? ks : qs;
        int w8 = wy & 7;
#pragma unroll
        for (int c = 0; c < 8; c++) {
            int n0 = w8 * 32 + c * 4;
            float t0v = src[(n0 + 0) * 32 + tx];
            float t1v = src[(n0 + 1) * 32 + tx];
            float t2v = src[(n0 + 2) * 32 + tx];
            float t3v = src[(n0 + 3) * 32 + tx];
            float4 val; val.x = t0v; val.y = t1v; val.z = t2v; val.w = t3v;
            *(float4*)(dst + tx * KST + n0) = val;
        }
    }
    __syncthreads();

    int b = w >> 8, wh = (w >> 4) & 15, ww = w & 15;

    for (int qt = 0; qt < 2; qt++) {
        int i0 = qt << 7;
        int mrow = i0 + wy * 8;

        // ---- GEMM1: S = q @ k^T ----
        u64 acc[4][8];
#pragma unroll
        for (int p = 0; p < 4; p++)
#pragma unroll
            for (int u = 0; u < 8; u++) acc[p][u] = 0ull;

#pragma unroll 4
        for (int d = 0; d < 32; d++) {
            const float* qrow = qs + d * KST + mrow;
            float4 ql = *(const float4*)qrow;
            float4 qh = *(const float4*)(qrow + 4);
            u64 qa[4];
            qa[0] = pk2(ql.x, ql.y); qa[1] = pk2(ql.z, ql.w);
            qa[2] = pk2(qh.x, qh.y); qa[3] = pk2(qh.z, qh.w);
            const float* krow = ks + d * KST + tx;
#pragma unroll
            for (int u = 0; u < 8; u++) {
                float kb = krow[32 * u];
                u64 b2 = pk2(kb, kb);
#pragma unroll
                for (int p = 0; p < 4; p++) fma2(acc[p][u], qa[p], b2);
            }
        }

        // ---- bias + register softmax ----
        float s[8][8];
#pragma unroll
        for (int p = 0; p < 4; p++)
#pragma unroll
            for (int u = 0; u < 8; u++) {
                float2 v = up2(acc[p][u]);
                s[2 * p][u] = v.x; s[2 * p + 1][u] = v.y;
            }
#pragma unroll
        for (int r = 0; r < 8; r++) {
            int i = mrow + r;
            int bi = ((i >> 4) + 15) * 31 + (i & 15) + 15;
#pragma unroll
            for (int u = 0; u < 8; u++) {
                int j = tx + 32 * u;
                s[r][u] += posh[bi - (j >> 4) * 31 - (j & 15)];
            }
        }
#pragma unroll
        for (int r = 0; r < 8; r++) {
            float mx = s[r][0];
#pragma unroll
            for (int u = 1; u < 8; u++) mx = fmaxf(mx, s[r][u]);
#pragma unroll
            for (int o = 16; o; o >>= 1) mx = fmaxf(mx, __shfl_xor_sync(0xffffffffu, mx, o));
            float sum = 0.f;
#pragma unroll
            for (int u = 0; u < 8; u++) {
                float e = __expf(s[r][u] - mx);
                s[r][u] = e; sum += e;
            }
#pragma unroll
            for (int o = 16; o; o >>= 1) sum += __shfl_xor_sync(0xffffffffu, sum, o);
            float inv = __fdividef(1.f, sum);
#pragma unroll
            for (int u = 0; u < 8; u++) s[r][u] *= inv;
        }

        // ---- store P^T bf16x2, swizzled for LDS.128 reads ----
#pragma unroll
        for (int u = 0; u < 8; u++) {
            int j = tx + 32 * u;
            int sw = ((wy ^ ((j >> 2) & 7)) << 2);
#pragma unroll
            for (int p = 0; p < 4; p++)
                Psu[j * PSTU + sw + p] = bf2pack(s[2 * p][u], s[2 * p + 1][u]);
        }
        __syncthreads();

        // ---- GEMM2: out = P @ v (4-way k-split) ----
        {
            int s4 = wy >> 2;
            int mg = tx >> 3, dg = tx & 7;
            int m0 = (wy & 3) * 32 + mg * 8;
            int bread = (wy & 3) * 4 + mg;
            u64 a2[4][4];
#pragma unroll
            for (int p = 0; p < 4; p++)
#pragma unroll
                for (int c = 0; c < 4; c++) a2[p][c] = 0ull;

#pragma unroll 4
            for (int kk = 0; kk < 64; kk++) {
                int k = s4 * 64 + kk;
                int xk = (k >> 2) & 7;
                uint4 pw = *(const uint4*)(Psu + k * PSTU + ((bread ^ xk) << 2));
                u64 pa[4];
#pragma unroll
                for (int p = 0; p < 4; p++) {
                    unsigned u32v = (p == 0) ? pw.x : (p == 1) ? pw.y : (p == 2) ? pw.z : pw.w;
                    pa[p] = pk2u(u32v << 16, u32v & 0xffff0000u);
                }
                float4 vv = *(const float4*)(vs + k * 32 + dg * 4);
                u64 b0 = pk2(vv.x, vv.x), b1 = pk2(vv.y, vv.y),
                    b2 = pk2(vv.z, vv.z), b3 = pk2(vv.w, vv.w);
#pragma unroll
                for (int p = 0; p < 4; p++) {
                    fma2(a2[p][0], pa[p], b0); fma2(a2[p][1], pa[p], b1);
                    fma2(a2[p][2], pa[p], b2); fma2(a2[p][3], pa[p], b3);
                }
            }
            __syncthreads();   // all P reads done; alias region as red
#pragma unroll
            for (int p = 0; p < 4; p++)
#pragma unroll
                for (int c = 0; c < 4; c++) {
                    float2 v = up2(a2[p][c]);
                    redf[((s4 << 7) + m0 + 2 * p) * RST + dg * 4 + c] = v.x;
                    redf[((s4 << 7) + m0 + 2 * p + 1) * RST + dg * 4 + c] = v.y;
                }
        }
        __syncthreads();

        // ---- combine k-splits + residual + store ----
        {
            int m = tid & 127, dq = tid >> 7;
            int i = i0 + m;
            int row = (b << 16) + (((wh << 4) + (i >> 4)) << 8) + (ww << 4) + (i & 15);
            float o[8];
#pragma unroll
            for (int c = 0; c < 8; c++)
                o[c] = redf[m * RST + dq * 8 + c]
                     + redf[((1 << 7) + m) * RST + dq * 8 + c]
                     + redf[((2 << 7) + m) * RST + dq * 8 + c]
                     + redf[((3 << 7) + m) * RST + dq * 8 + c];
            const float* xr = x + (size_t)row * 128 + h * 32 + dq * 8;
            float* orr = out + (size_t)row * 128 + h * 32 + dq * 8;
            float4 x1 = *(const float4*)xr;
            float4 x2 = *(const float4*)(xr + 4);
            float4 o1; o1.x = o[0] + x1.x; o1.y = o[1] + x1.y; o1.z = o[2] + x1.z; o1.w = o[3] + x1.w;
            float4 o2; o2.x = o[4] + x2.x; o2.y = o[5] + x2.y; o2.z = o[6] + x2.z; o2.w = o[7] + x2.w;
            *(float4*)orr = o1;
            *(float4*)(orr + 4) = o2;
        }
        __syncthreads();
    }
}

// ---------------- launch ----------------
extern "C" void kernel_launch(void* const* d_in, const int* in_sizes, int n_in,
                              void* d_out, int out_size)
{
    (void)in_sizes; (void)n_in; (void)out_size;
    const float* x      = (const float*)d_in[0];
    const float* n1g    = (const float*)d_in[1];
    const float* n1b    = (const float*)d_in[2];
    const float* qkv_w  = (const float*)d_in[3];
    const float* qkv_b  = (const float*)d_in[4];
    const float* pp_w   = (const float*)d_in[5];
    const float* pp_b   = (const float*)d_in[6];
    const float* l1_g   = (const float*)d_in[7];
    const float* l1_b   = (const float*)d_in[8];
    const float* f1_w   = (const float*)d_in[9];
    const float* f1_b   = (const float*)d_in[10];
    const float* l2_g   = (const float*)d_in[11];
    const float* l2_b   = (const float*)d_in[12];
    const float* f2_w   = (const float*)d_in[13];
    const float* f2_b   = (const float*)d_in[14];
    const float* l3_g   = (const float*)d_in[15];
    const float* l3_b   = (const float*)d_in[16];
    const float* f3_w   = (const float*)d_in[17];
    const float* f3_b   = (const float*)d_in[18];
    float* out = (float*)d_out;

    const int qkv_smem  = QKV_SMEM_FLOATS * 4;    // 132,608 B
    const int attn_smem = ATTN_SMEM_FLOATS * 4;   // 172,816 B
    cudaFuncSetAttribute(qkv_kernel,  cudaFuncAttributeMaxDynamicSharedMemorySize, qkv_smem);
    cudaFuncSetAttribute(attn_kernel, cudaFuncAttributeMaxDynamicSharedMemorySize, attn_smem);

    prep_pos_kernel<<<1, 1024>>>(pp_w, pp_b, l1_g, l1_b, f1_w, f1_b,
                                 l2_g, l2_b, f2_w, f2_b, l3_g, l3_b, f3_w, f3_b);
    prep_w_kernel<<<384, 128>>>(qkv_w, qkv_b, n1g, n1b);
    qkv_kernel<<<2048, 512, qkv_smem>>>(x);
    attn_kernel<<<2048, 512, attn_smem>>>(x, out);
}

// round 6
// speedup vs baseline: 3.3787x; 3.3787x over previous
#include <cuda_runtime.h>
#include <cuda_bf16.h>
#include <math.h>
#include <cstdint>

#define HEADS   4
#define NTOK    256
#define NWIN    512
#define POSN    961
#define QKSCALE 0.17677669529663689f
#define LOG2E   1.4426950408889634f

// ---------------- scratch ----------------
__device__ unsigned short g_q[NWIN * HEADS * NTOK * 32];
__device__ unsigned short g_k[NWIN * HEADS * NTOK * 32];
__device__ unsigned short g_v[NWIN * HEADS * NTOK * 32];
__device__ unsigned short g_wb[384 * 128];     // bf16 gamma-folded W, [j][k]
__device__ float g_cs[384];
__device__ float g_cb[384];
__device__ float g_pos[HEADS * POSN];          // pre-multiplied by LOG2E
__device__ float g_bias[HEADS * 256 * 256];    // expanded bias table (log2 units)

// ---------------- helpers ----------------
__device__ __forceinline__ uint32_t bf2pack(float lo, float hi) {
    uint32_t r; asm("cvt.rn.bf16x2.f32 %0,%1,%2;" : "=r"(r) : "f"(hi), "f"(lo)); return r;
}
__device__ __forceinline__ uint32_t smem_u32(const void* p) {
    uint32_t a;
    asm("{ .reg .u64 t; cvta.to.shared.u64 t, %1; cvt.u32.u64 %0, t; }" : "=r"(a) : "l"(p));
    return a;
}
__device__ __forceinline__ void ldmx4(uint32_t* r, uint32_t addr) {
    asm volatile("ldmatrix.sync.aligned.m8n8.x4.shared.b16 {%0,%1,%2,%3}, [%4];"
        : "=r"(r[0]), "=r"(r[1]), "=r"(r[2]), "=r"(r[3]) : "r"(addr));
}
__device__ __forceinline__ void mma16816(float* c, const uint32_t* a, const uint32_t* b) {
    asm volatile("mma.sync.aligned.m16n8k16.row.col.f32.bf16.bf16.f32 "
        "{%0,%1,%2,%3},{%4,%5,%6,%7},{%8,%9},{%0,%1,%2,%3};"
        : "+f"(c[0]), "+f"(c[1]), "+f"(c[2]), "+f"(c[3])
        : "r"(a[0]), "r"(a[1]), "r"(a[2]), "r"(a[3]), "r"(b[0]), "r"(b[1]));
}
__device__ __forceinline__ float ex2f(float x) {
    float r; asm("ex2.approx.ftz.f32 %0,%1;" : "=f"(r) : "f"(x)); return r;
}

// ---------------- pos-bias MLP ----------------
__device__ __forceinline__ void ln_relu8(float* a, const float* g, const float* b) {
    float m = 0.f;
#pragma unroll
    for (int u = 0; u < 8; u++) m += a[u];
    m *= 0.125f;
    float v = 0.f;
#pragma unroll
    for (int u = 0; u < 8; u++) { float d = a[u] - m; v += d * d; }
    v *= 0.125f;
    float r = rsqrtf(v + 1e-5f);
#pragma unroll
    for (int u = 0; u < 8; u++) a[u] = fmaxf((a[u] - m) * r * g[u] + b[u], 0.f);
}
__device__ __forceinline__ void fc8(const float* a, float* y, const float* w, const float* b) {
#pragma unroll
    for (int o = 0; o < 8; o++) {
        float s = b[o];
#pragma unroll
        for (int u = 0; u < 8; u++) s += a[u] * w[o * 8 + u];
        y[o] = s;
    }
}

__global__ void prep_pos_kernel(
    const float* __restrict__ pp_w, const float* __restrict__ pp_b,
    const float* __restrict__ l1_g, const float* __restrict__ l1_b,
    const float* __restrict__ f1_w, const float* __restrict__ f1_b,
    const float* __restrict__ l2_g, const float* __restrict__ l2_b,
    const float* __restrict__ f2_w, const float* __restrict__ f2_b,
    const float* __restrict__ l3_g, const float* __restrict__ l3_b,
    const float* __restrict__ f3_w, const float* __restrict__ f3_b)
{
    int p = blockIdx.x * blockDim.x + threadIdx.x;
    if (p >= POSN) return;
    float bh = (float)(p / 31 - 15);
    float bw = (float)(p % 31 - 15);
    float a[8], y[8];
#pragma unroll
    for (int u = 0; u < 8; u++) a[u] = bh * pp_w[2 * u] + bw * pp_w[2 * u + 1] + pp_b[u];
    ln_relu8(a, l1_g, l1_b);
    fc8(a, y, f1_w, f1_b);
    ln_relu8(y, l2_g, l2_b);
    fc8(y, a, f2_w, f2_b);
    ln_relu8(a, l3_g, l3_b);
#pragma unroll
    for (int hh = 0; hh < HEADS; hh++) {
        float s = f3_b[hh];
#pragma unroll
        for (int u = 0; u < 8; u++) s += a[u] * f3_w[hh * 8 + u];
        g_pos[hh * POSN + p] = s * LOG2E;
    }
}

__global__ void bias_expand_kernel() {
    int i = blockIdx.x, h = blockIdx.y, j = threadIdx.x;
    int dih = (i >> 4) - (j >> 4) + 15;
    int diw = (i & 15) - (j & 15) + 15;
    g_bias[((h << 8) + i) * 256 + j] = g_pos[h * POSN + dih * 31 + diw];
}

// ---------------- fold LN gamma into W, bf16 ----------------
__global__ void prep_w_kernel(const float* __restrict__ qkv_w, const float* __restrict__ qkv_b,
                              const float* __restrict__ g1, const float* __restrict__ b1)
{
    __shared__ float s1[128], s2[128];
    int j = blockIdx.x;
    int k = threadIdx.x;
    float w = qkv_w[j * 128 + k];
    float wg = w * g1[k];
    __nv_bfloat16 wbh = __float2bfloat16(wg);
    g_wb[j * 128 + k] = *(unsigned short*)&wbh;
    s1[k] = __bfloat162float(wbh);     // column sum of ROUNDED weights
    s2[k] = w * b1[k];
    __syncthreads();
    for (int o = 64; o > 0; o >>= 1) {
        if (k < o) { s1[k] += s1[k + o]; s2[k] += s2[k + o]; }
        __syncthreads();
    }
    if (k == 0) {
        float cb = s2[0] + qkv_b[j];
        if (j < 128) cb *= QKSCALE * LOG2E;   // prescale q bias
        g_cs[j] = s1[0];
        g_cb[j] = cb;
    }
}

// ---------------- QKV GEMM via mma.sync (fused LN analytic) ----------------
// smem layout (bytes)
#define QX_XB   0                       // 128 rows x 272B (136 bf16 stride)
#define QX_WB   34816                   // 384 rows x 272B
#define QX_CS   139264
#define QX_CB   140800
#define QX_MEAN 142336
#define QX_RSTD 142848
#define QKV_SMEM 143360

__global__ __launch_bounds__(256, 1) void qkv_kernel(const float* __restrict__ x)
{
    extern __shared__ char smc[];
    uint32_t sb = smem_u32(smc);
    float* scs   = (float*)(smc + QX_CS);
    float* scb   = (float*)(smc + QX_CB);
    float* smean = (float*)(smc + QX_MEAN);
    float* srstd = (float*)(smc + QX_RSTD);

    int tid = threadIdx.x;
    int wid = tid >> 5, lane = tid & 31;
    int t0 = blockIdx.x * 128;

    // stage Wb: 384 rows x 256B -> stride 272B
    {
        const uint4* src = (const uint4*)g_wb;
#pragma unroll
        for (int i = 0; i < 24; i++) {
            int f = i * 256 + tid;             // 6144 uint4
            int j = f >> 4, c = f & 15;
            *(uint4*)(smc + QX_WB + j * 272 + c * 16) = src[f];
        }
    }
    for (int p = tid; p < 384; p += 256) { scs[p] = g_cs[p]; scb[p] = g_cb[p]; }

    // load x rows (gathered), LN stats, convert to bf16
    {
        int row = tid >> 1, half = tid & 1;
        int t = t0 + row;
        int w = t >> 8, n = t & 255;
        int imgrow = ((w >> 8) << 16) + (((((w >> 4) & 15) << 4) + (n >> 4)) << 8)
                   + ((w & 15) << 4) + (n & 15);
        const float4* src4 = (const float4*)(x + (size_t)imgrow * 128 + half * 64);
        float s = 0.f, q = 0.f;
#pragma unroll
        for (int i = 0; i < 8; i++) {
            float4 a = src4[2 * i], b = src4[2 * i + 1];
            s += a.x + a.y + a.z + a.w + b.x + b.y + b.z + b.w;
            q += a.x*a.x + a.y*a.y + a.z*a.z + a.w*a.w + b.x*b.x + b.y*b.y + b.z*b.z + b.w*b.w;
            uint4 o;
            o.x = bf2pack(a.x, a.y); o.y = bf2pack(a.z, a.w);
            o.z = bf2pack(b.x, b.y); o.w = bf2pack(b.z, b.w);
            *(uint4*)(smc + QX_XB + row * 272 + half * 128 + i * 16) = o;
        }
        s += __shfl_xor_sync(0xffffffffu, s, 1);
        q += __shfl_xor_sync(0xffffffffu, q, 1);
        if (half == 0) {
            float mu = s * (1.f / 128.f);
            smean[row] = mu;
            srstd[row] = rsqrtf(q * (1.f / 128.f) - mu * mu + 1e-5f);
        }
    }
    __syncthreads();

    // A fragments for this warp's 16 rows (k = 128 -> 8 k-steps)
    uint32_t af[8][4];
#pragma unroll
    for (int kt = 0; kt < 8; kt++) {
        uint32_t addr = sb + QX_XB
            + (wid * 16 + (lane & 7) + ((lane >> 3) & 1) * 8) * 272
            + (kt * 16 + ((lane >> 3) >> 1) * 8) * 2;
        ldmx4(af[kt], addr);
    }
    float mean0 = smean[wid * 16 + (lane >> 2)];
    float mean1 = smean[wid * 16 + (lane >> 2) + 8];
    float is0 = srstd[wid * 16 + (lane >> 2)];
    float is1 = srstd[wid * 16 + (lane >> 2) + 8];
    float is0q = is0 * (QKSCALE * LOG2E), is1q = is1 * (QKSCALE * LOG2E);

    int wv = blockIdx.x >> 1;
    int nbase = (blockIdx.x & 1) * 128 + wid * 16 + (lane >> 2);

    for (int nj = 0; nj < 48; nj++) {
        uint32_t bf[4][4];
#pragma unroll
        for (int i = 0; i < 4; i++) {
            uint32_t addr = sb + QX_WB + (nj * 8 + (lane & 7)) * 272
                          + (32 * i + (lane >> 3) * 8) * 2;
            ldmx4(bf[i], addr);
        }
        float c[4] = {0.f, 0.f, 0.f, 0.f};
#pragma unroll
        for (int i = 0; i < 4; i++) {
            mma16816(c, af[2 * i],     &bf[i][0]);
            mma16816(c, af[2 * i + 1], &bf[i][2]);
        }
        int j0 = nj * 8 + 2 * (lane & 3);
        float2 cs2 = *(float2*)(scs + j0);
        float2 cb2 = *(float2*)(scb + j0);
        float ia = (nj < 16) ? is0q : is0;
        float ib = (nj < 16) ? is1q : is1;
        float v00 = ia * (c[0] - mean0 * cs2.x) + cb2.x;
        float v01 = ia * (c[1] - mean0 * cs2.y) + cb2.y;
        float v10 = ib * (c[2] - mean1 * cs2.x) + cb2.x;
        float v11 = ib * (c[3] - mean1 * cs2.y) + cb2.y;
        int head = (j0 >> 5) & 3;
        int d0 = j0 & 31;
        unsigned short* dst = (j0 < 128) ? g_q : (j0 < 256) ? g_k : g_v;
        size_t o = ((size_t)(wv * 4 + head) * 256 + nbase) * 32 + d0;
        *(uint32_t*)(dst + o)            = bf2pack(v00, v01);
        *(uint32_t*)(dst + o + 8 * 32)   = bf2pack(v10, v11);
    }
}

// ---------------- attention via mma.sync ----------------
// smem: Qs [256][40bf16=80B], Ks same, Vt [32][264bf16=528B]
#define AT_QS 0
#define AT_KS 20480
#define AT_VT 40960
#define ATTN_SMEM 57856

__global__ __launch_bounds__(256, 1) void attn_kernel(const float* __restrict__ x,
                                                      float* __restrict__ out)
{
    extern __shared__ char smc[];
    uint32_t sb = smem_u32(smc);
    int tid = threadIdx.x;
    int wid = tid >> 5, lane = tid & 31;
    int w = blockIdx.x >> 2, h = blockIdx.x & 3;
    size_t gbase = (size_t)(w * 4 + h) * (256 * 32);

    // Qs/Ks: [256][40] bf16 (row = token, 32 d + pad)
    {
        const uint4* qsrc = (const uint4*)(g_q + gbase);
        const uint4* ksrc = (const uint4*)(g_k + gbase);
#pragma unroll
        for (int i = 0; i < 4; i++) {
            int c = i * 256 + tid;             // 1024 uint4
            int n = c >> 2, ch = c & 3;
            *(uint4*)(smc + AT_QS + n * 80 + ch * 16) = qsrc[c];
            *(uint4*)(smc + AT_KS + n * 80 + ch * 16) = ksrc[c];
        }
    }
    // Vt: [32 d][264 tok] bf16 transpose
    {
        const uint4* vsrc = (const uint4*)(g_v + gbase);
#pragma unroll
        for (int i = 0; i < 2; i++) {
            int s = i * 256 + tid;             // 512 tasks
            int np = s >> 2, dg = s & 3;
            int n = np * 2;
            uint4 A = vsrc[n * 4 + dg];
            uint4 B = vsrc[(n + 1) * 4 + dg];
            uint32_t aw[4] = {A.x, A.y, A.z, A.w};
            uint32_t bw[4] = {B.x, B.y, B.z, B.w};
#pragma unroll
            for (int dd = 0; dd < 8; dd++) {
                uint32_t o32 = (dd & 1) ? __byte_perm(aw[dd >> 1], bw[dd >> 1], 0x7632)
                                        : __byte_perm(aw[dd >> 1], bw[dd >> 1], 0x5410);
                int d = dg * 8 + dd;
                *(uint32_t*)(smc + AT_VT + (d * 264 + n) * 2) = o32;
            }
        }
    }
    __syncthreads();

    int b_ = w >> 8, wh = (w >> 4) & 15, ww = w & 15;

    for (int p = 0; p < 2; p++) {
        int r0 = p * 128 + wid * 16;

        // ---- GEMM1: S[16][256] = Q @ K^T ----
        uint32_t af[2][4];
#pragma unroll
        for (int kt = 0; kt < 2; kt++) {
            uint32_t addr = sb + AT_QS
                + (r0 + (lane & 7) + ((lane >> 3) & 1) * 8) * 80
                + (kt * 16 + ((lane >> 3) >> 1) * 8) * 2;
            ldmx4(af[kt], addr);
        }
        float S[32][4];
#pragma unroll
        for (int nc = 0; nc < 32; nc++) {
            S[nc][0] = 0.f; S[nc][1] = 0.f; S[nc][2] = 0.f; S[nc][3] = 0.f;
            uint32_t bfr[4];
            uint32_t addr = sb + AT_KS + (nc * 8 + (lane & 7)) * 80 + (lane >> 3) * 16;
            ldmx4(bfr, addr);
            mma16816(S[nc], af[0], &bfr[0]);
            mma16816(S[nc], af[1], &bfr[2]);
        }

        // ---- bias (global table) + row max ----
        int row0 = r0 + (lane >> 2);
        const float* bp0 = g_bias + ((size_t)(h * 256 + row0) << 8) + 2 * (lane & 3);
        const float* bp1 = bp0 + (8 << 8);
        float mx0 = -1e30f, mx1 = -1e30f;
#pragma unroll
        for (int nc = 0; nc < 32; nc++) {
            float2 b0 = *(const float2*)(bp0 + nc * 8);
            float2 b1 = *(const float2*)(bp1 + nc * 8);
            S[nc][0] += b0.x; S[nc][1] += b0.y;
            S[nc][2] += b1.x; S[nc][3] += b1.y;
            mx0 = fmaxf(mx0, fmaxf(S[nc][0], S[nc][1]));
            mx1 = fmaxf(mx1, fmaxf(S[nc][2], S[nc][3]));
        }
        mx0 = fmaxf(mx0, __shfl_xor_sync(0xffffffffu, mx0, 1));
        mx0 = fmaxf(mx0, __shfl_xor_sync(0xffffffffu, mx0, 2));
        mx1 = fmaxf(mx1, __shfl_xor_sync(0xffffffffu, mx1, 1));
        mx1 = fmaxf(mx1, __shfl_xor_sync(0xffffffffu, mx1, 2));

        // ---- exp (log2 domain) + pack P to bf16 A-frags ----
        uint32_t paA[32], paB[32];
        float sum0 = 0.f, sum1 = 0.f;
#pragma unroll
        for (int nc = 0; nc < 32; nc++) {
            float e0 = ex2f(S[nc][0] - mx0);
            float e1 = ex2f(S[nc][1] - mx0);
            float e2 = ex2f(S[nc][2] - mx1);
            float e3 = ex2f(S[nc][3] - mx1);
            sum0 += e0 + e1; sum1 += e2 + e3;
            paA[nc] = bf2pack(e0, e1);
            paB[nc] = bf2pack(e2, e3);
        }
        sum0 += __shfl_xor_sync(0xffffffffu, sum0, 1);
        sum0 += __shfl_xor_sync(0xffffffffu, sum0, 2);
        sum1 += __shfl_xor_sync(0xffffffffu, sum1, 1);
        sum1 += __shfl_xor_sync(0xffffffffu, sum1, 2);
        float inv0, inv1;
        asm("rcp.approx.ftz.f32 %0,%1;" : "=f"(inv0) : "f"(sum0));
        asm("rcp.approx.ftz.f32 %0,%1;" : "=f"(inv1) : "f"(sum1));

        // ---- GEMM2: O[16][32] = P @ V ----
        float O[4][4];
#pragma unroll
        for (int nc2 = 0; nc2 < 4; nc2++) {
            O[nc2][0] = 0.f; O[nc2][1] = 0.f; O[nc2][2] = 0.f; O[nc2][3] = 0.f;
#pragma unroll
            for (int kg = 0; kg < 8; kg++) {
                uint32_t bfr[4];
                uint32_t addr = sb + AT_VT + (nc2 * 8 + (lane & 7)) * 528
                              + (kg * 32 + (lane >> 3) * 8) * 2;
                ldmx4(bfr, addr);
                uint32_t a0[4] = {paA[4 * kg],     paB[4 * kg],     paA[4 * kg + 1], paB[4 * kg + 1]};
                uint32_t a1[4] = {paA[4 * kg + 2], paB[4 * kg + 2], paA[4 * kg + 3], paB[4 * kg + 3]};
                mma16816(O[nc2], a0, &bfr[0]);
                mma16816(O[nc2], a1, &bfr[2]);
            }
        }

        // ---- epilogue: 1/sum, residual, store ----
        int n0 = row0;
        int n1 = row0 + 8;
        int ir0 = (b_ << 16) + (((wh << 4) + (n0 >> 4)) << 8) + (ww << 4) + (n0 & 15);
        int ir1 = (b_ << 16) + (((wh << 4) + (n1 >> 4)) << 8) + (ww << 4) + (n1 & 15);
        const float* xr0 = x + (size_t)ir0 * 128 + h * 32;
        const float* xr1 = x + (size_t)ir1 * 128 + h * 32;
        float* or0 = out + (size_t)ir0 * 128 + h * 32;
        float* or1 = out + (size_t)ir1 * 128 + h * 32;
#pragma unroll
        for (int nc2 = 0; nc2 < 4; nc2++) {
            int d0 = nc2 * 8 + 2 * (lane & 3);
            float2 xv0 = *(const float2*)(xr0 + d0);
            float2 xv1 = *(const float2*)(xr1 + d0);
            float2 o0, o1;
            o0.x = O[nc2][0] * inv0 + xv0.x;
            o0.y = O[nc2][1] * inv0 + xv0.y;
            o1.x = O[nc2][2] * inv1 + xv1.x;
            o1.y = O[nc2][3] * inv1 + xv1.y;
            *(float2*)(or0 + d0) = o0;
            *(float2*)(or1 + d0) = o1;
        }
    }
}

// ---------------- launch ----------------
extern "C" void kernel_launch(void* const* d_in, const int* in_sizes, int n_in,
                              void* d_out, int out_size)
{
    (void)in_sizes; (void)n_in; (void)out_size;
    const float* x      = (const float*)d_in[0];
    const float* n1g    = (const float*)d_in[1];
    const float* n1b    = (const float*)d_in[2];
    const float* qkv_w  = (const float*)d_in[3];
    const float* qkv_b  = (const float*)d_in[4];
    const float* pp_w   = (const float*)d_in[5];
    const float* pp_b   = (const float*)d_in[6];
    const float* l1_g   = (const float*)d_in[7];
    const float* l1_b   = (const float*)d_in[8];
    const float* f1_w   = (const float*)d_in[9];
    const float* f1_b   = (const float*)d_in[10];
    const float* l2_g   = (const float*)d_in[11];
    const float* l2_b   = (const float*)d_in[12];
    const float* f2_w   = (const float*)d_in[13];
    const float* f2_b   = (const float*)d_in[14];
    const float* l3_g   = (const float*)d_in[15];
    const float* l3_b   = (const float*)d_in[16];
    const float* f3_w   = (const float*)d_in[17];
    const float* f3_b   = (const float*)d_in[18];
    float* out = (float*)d_out;

    cudaFuncSetAttribute(qkv_kernel,  cudaFuncAttributeMaxDynamicSharedMemorySize, QKV_SMEM);
    cudaFuncSetAttribute(attn_kernel, cudaFuncAttributeMaxDynamicSharedMemorySize, ATTN_SMEM);

    prep_pos_kernel<<<1, 1024>>>(pp_w, pp_b, l1_g, l1_b, f1_w, f1_b,
                                 l2_g, l2_b, f2_w, f2_b, l3_g, l3_b, f3_w, f3_b);
    bias_expand_kernel<<<dim3(256, 4), 256>>>();
    prep_w_kernel<<<384, 128>>>(qkv_w, qkv_b, n1g, n1b);
    qkv_kernel<<<1024, 256, QKV_SMEM>>>(x);
    attn_kernel<<<2048, 256, ATTN_SMEM>>>(x, out);
}

// round 8
// speedup vs baseline: 4.1322x; 1.2230x over previous
#include <cuda_runtime.h>
#include <cuda_bf16.h>
#include <math.h>
#include <cstdint>

#define HEADS   4
#define NTOK    256
#define NWIN    512
#define POSN    961
#define QKSCALE 0.17677669529663689f
#define LOG2E   1.4426950408889634f

// ---------------- scratch ----------------
__device__ unsigned short g_q[NWIN * HEADS * NTOK * 32];
__device__ unsigned short g_k[NWIN * HEADS * NTOK * 32];
__device__ unsigned short g_v[NWIN * HEADS * NTOK * 32];
__device__ unsigned short g_wb[384 * 128];     // bf16 gamma-folded W, [j][k]
__device__ float g_cs[384];
__device__ float g_cb[384];
__device__ float g_pos[HEADS * POSN];          // pre-multiplied by LOG2E

// ---------------- helpers ----------------
__device__ __forceinline__ uint32_t bf2pack(float lo, float hi) {
    uint32_t r; asm("cvt.rn.bf16x2.f32 %0,%1,%2;" : "=r"(r) : "f"(hi), "f"(lo)); return r;
}
__device__ __forceinline__ uint32_t smem_u32(const void* p) {
    uint32_t a;
    asm("{ .reg .u64 t; cvta.to.shared.u64 t, %1; cvt.u32.u64 %0, t; }" : "=r"(a) : "l"(p));
    return a;
}
__device__ __forceinline__ void ldmx4(uint32_t* r, uint32_t addr) {
    asm volatile("ldmatrix.sync.aligned.m8n8.x4.shared.b16 {%0,%1,%2,%3}, [%4];"
        : "=r"(r[0]), "=r"(r[1]), "=r"(r[2]), "=r"(r[3]) : "r"(addr));
}
__device__ __forceinline__ void mma16816(float* c, const uint32_t* a, const uint32_t* b) {
    asm volatile("mma.sync.aligned.m16n8k16.row.col.f32.bf16.bf16.f32 "
        "{%0,%1,%2,%3},{%4,%5,%6,%7},{%8,%9},{%0,%1,%2,%3};"
        : "+f"(c[0]), "+f"(c[1]), "+f"(c[2]), "+f"(c[3])
        : "r"(a[0]), "r"(a[1]), "r"(a[2]), "r"(a[3]), "r"(b[0]), "r"(b[1]));
}
__device__ __forceinline__ float ex2f(float x) {
    float r; asm("ex2.approx.ftz.f32 %0,%1;" : "=f"(r) : "f"(x)); return r;
}

// ---------------- pos-bias MLP ----------------
__device__ __forceinline__ void ln_relu8(float* a, const float* g, const float* b) {
    float m = 0.f;
#pragma unroll
    for (int u = 0; u < 8; u++) m += a[u];
    m *= 0.125f;
    float v = 0.f;
#pragma unroll
    for (int u = 0; u < 8; u++) { float d = a[u] - m; v += d * d; }
    v *= 0.125f;
    float r = rsqrtf(v + 1e-5f);
#pragma unroll
    for (int u = 0; u < 8; u++) a[u] = fmaxf((a[u] - m) * r * g[u] + b[u], 0.f);
}
__device__ __forceinline__ void fc8(const float* a, float* y, const float* w, const float* b) {
#pragma unroll
    for (int o = 0; o < 8; o++) {
        float s = b[o];
#pragma unroll
        for (int u = 0; u < 8; u++) s += a[u] * w[o * 8 + u];
        y[o] = s;
    }
}

__global__ void prep_pos_kernel(
    const float* __restrict__ pp_w, const float* __restrict__ pp_b,
    const float* __restrict__ l1_g, const float* __restrict__ l1_b,
    const float* __restrict__ f1_w, const float* __restrict__ f1_b,
    const float* __restrict__ l2_g, const float* __restrict__ l2_b,
    const float* __restrict__ f2_w, const float* __restrict__ f2_b,
    const float* __restrict__ l3_g, const float* __restrict__ l3_b,
    const float* __restrict__ f3_w, const float* __restrict__ f3_b)
{
    int p = blockIdx.x * blockDim.x + threadIdx.x;
    if (p >= POSN) return;
    float bh = (float)(p / 31 - 15);
    float bw = (float)(p % 31 - 15);
    float a[8], y[8];
#pragma unroll
    for (int u = 0; u < 8; u++) a[u] = bh * pp_w[2 * u] + bw * pp_w[2 * u + 1] + pp_b[u];
    ln_relu8(a, l1_g, l1_b);
    fc8(a, y, f1_w, f1_b);
    ln_relu8(y, l2_g, l2_b);
    fc8(y, a, f2_w, f2_b);
    ln_relu8(a, l3_g, l3_b);
#pragma unroll
    for (int hh = 0; hh < HEADS; hh++) {
        float s = f3_b[hh];
#pragma unroll
        for (int u = 0; u < 8; u++) s += a[u] * f3_w[hh * 8 + u];
        g_pos[hh * POSN + p] = s * LOG2E;
    }
}

// ---------------- fold LN gamma into W, bf16 ----------------
__global__ void prep_w_kernel(const float* __restrict__ qkv_w, const float* __restrict__ qkv_b,
                              const float* __restrict__ g1, const float* __restrict__ b1)
{
    __shared__ float s1[128], s2[128];
    int j = blockIdx.x;
    int k = threadIdx.x;
    float w = qkv_w[j * 128 + k];
    float wg = w * g1[k];
    __nv_bfloat16 wbh = __float2bfloat16(wg);
    g_wb[j * 128 + k] = *(unsigned short*)&wbh;
    s1[k] = __bfloat162float(wbh);
    s2[k] = w * b1[k];
    __syncthreads();
    for (int o = 64; o > 0; o >>= 1) {
        if (k < o) { s1[k] += s1[k + o]; s2[k] += s2[k + o]; }
        __syncthreads();
    }
    if (k == 0) {
        float cb = s2[0] + qkv_b[j];
        if (j < 128) cb *= QKSCALE * LOG2E;
        g_cs[j] = s1[0];
        g_cb[j] = cb;
    }
}

// ---------------- QKV GEMM (64 rows x 384 cols per CTA, 32x96 warp tiles) ----------------
#define QX_XB   0                       // 64 rows x 272B
#define QX_WB   17408                   // 384 rows x 272B
#define QX_CS   121856
#define QX_CB   123392
#define QX_MEAN 124928
#define QX_RSTD 125184
#define QKV_SMEM 125440

__global__ __launch_bounds__(256, 1) void qkv_kernel(const float* __restrict__ x)
{
    extern __shared__ char smc[];
    uint32_t sb = smem_u32(smc);
    float* scs   = (float*)(smc + QX_CS);
    float* scb   = (float*)(smc + QX_CB);
    float* smean = (float*)(smc + QX_MEAN);
    float* srstd = (float*)(smc + QX_RSTD);

    int tid = threadIdx.x;
    int wid = tid >> 5, lane = tid & 31;
    int t0 = blockIdx.x * 64;

    // stage Wb: 384 rows x 256B -> stride 272B
    {
        const uint4* src = (const uint4*)g_wb;
#pragma unroll
        for (int i = 0; i < 24; i++) {
            int f = i * 256 + tid;             // 6144 uint4
            int j = f >> 4, c = f & 15;
            *(uint4*)(smc + QX_WB + j * 272 + c * 16) = src[f];
        }
    }
    for (int p = tid; p < 384; p += 256) { scs[p] = g_cs[p]; scb[p] = g_cb[p]; }

    // load 64 x rows (4 threads per row), LN stats, bf16 convert
    {
        int row = tid >> 2, qtr = tid & 3;
        int t = t0 + row;
        int w = t >> 8, n = t & 255;
        int imgrow = ((w >> 8) << 16) + (((((w >> 4) & 15) << 4) + (n >> 4)) << 8)
                   + ((w & 15) << 4) + (n & 15);
        const float4* src4 = (const float4*)(x + (size_t)imgrow * 128 + qtr * 32);
        float s = 0.f, q = 0.f;
#pragma unroll
        for (int i = 0; i < 4; i++) {
            float4 a = src4[2 * i], b = src4[2 * i + 1];
            s += a.x + a.y + a.z + a.w + b.x + b.y + b.z + b.w;
            q += a.x*a.x + a.y*a.y + a.z*a.z + a.w*a.w + b.x*b.x + b.y*b.y + b.z*b.z + b.w*b.w;
            uint4 o;
            o.x = bf2pack(a.x, a.y); o.y = bf2pack(a.z, a.w);
            o.z = bf2pack(b.x, b.y); o.w = bf2pack(b.z, b.w);
            *(uint4*)(smc + QX_XB + row * 272 + qtr * 64 + i * 16) = o;
        }
        s += __shfl_xor_sync(0xffffffffu, s, 1);
        q += __shfl_xor_sync(0xffffffffu, q, 1);
        s += __shfl_xor_sync(0xffffffffu, s, 2);
        q += __shfl_xor_sync(0xffffffffu, q, 2);
        if ((lane & 3) == 0) {
            float mu = s * (1.f / 128.f);
            smean[row] = mu;
            srstd[row] = rsqrtf(q * (1.f / 128.f) - mu * mu + 1e-5f);
        }
    }
    __syncthreads();

    int rg = wid >> 2, cg = wid & 3;   // row-group (2x32), col-group (4x96)

    float c[2][12][4];
#pragma unroll
    for (int t = 0; t < 2; t++)
#pragma unroll
        for (int nj = 0; nj < 12; nj++) {
            c[t][nj][0] = 0.f; c[t][nj][1] = 0.f; c[t][nj][2] = 0.f; c[t][nj][3] = 0.f;
        }

    for (int kk = 0; kk < 4; kk++) {   // k32 chunks
        uint32_t af[2][2][4];
#pragma unroll
        for (int t = 0; t < 2; t++)
#pragma unroll
            for (int ks = 0; ks < 2; ks++) {
                uint32_t addr = sb + QX_XB
                    + (rg * 32 + t * 16 + (lane & 7) + ((lane >> 3) & 1) * 8) * 272
                    + (kk * 32 + ks * 16 + (lane >> 4) * 8) * 2;
                ldmx4(af[t][ks], addr);
            }
#pragma unroll
        for (int nj = 0; nj < 12; nj++) {
            uint32_t bfr[4];
            uint32_t addr = sb + QX_WB + (cg * 96 + nj * 8 + (lane & 7)) * 272
                          + (kk * 32 + (lane >> 3) * 8) * 2;
            ldmx4(bfr, addr);
            mma16816(c[0][nj], af[0][0], &bfr[0]);
            mma16816(c[0][nj], af[0][1], &bfr[2]);
            mma16816(c[1][nj], af[1][0], &bfr[0]);
            mma16816(c[1][nj], af[1][1], &bfr[2]);
        }
    }

    // epilogue
    float mn[2][2], rs[2][2];
#pragma unroll
    for (int t = 0; t < 2; t++) {
        int lr = rg * 32 + t * 16 + (lane >> 2);
        mn[t][0] = smean[lr];     mn[t][1] = smean[lr + 8];
        rs[t][0] = srstd[lr];     rs[t][1] = srstd[lr + 8];
    }
    int wv = blockIdx.x >> 2;
    int nloc0 = (blockIdx.x & 3) * 64 + rg * 32 + (lane >> 2);
#pragma unroll
    for (int nj = 0; nj < 12; nj++) {
        int j0 = cg * 96 + nj * 8 + 2 * (lane & 3);
        float2 cs2 = *(float2*)(scs + j0);
        float2 cb2 = *(float2*)(scb + j0);
        int head = (j0 >> 5) & 3;
        int d0 = j0 & 31;
        unsigned short* dst = (j0 < 128) ? g_q : (j0 < 256) ? g_k : g_v;
        float qsc = (j0 < 128) ? (QKSCALE * LOG2E) : 1.f;
#pragma unroll
        for (int t = 0; t < 2; t++) {
            float ia = rs[t][0] * qsc, ib = rs[t][1] * qsc;
            float v00 = ia * (c[t][nj][0] - mn[t][0] * cs2.x) + cb2.x;
            float v01 = ia * (c[t][nj][1] - mn[t][0] * cs2.y) + cb2.y;
            float v10 = ib * (c[t][nj][2] - mn[t][1] * cs2.x) + cb2.x;
            float v11 = ib * (c[t][nj][3] - mn[t][1] * cs2.y) + cb2.y;
            int n = nloc0 + t * 16;
            size_t o = ((size_t)(wv * 4 + head) * 256 + n) * 32 + d0;
            *(uint32_t*)(dst + o)          = bf2pack(v00, v01);
            *(uint32_t*)(dst + o + 8 * 32) = bf2pack(v10, v11);
        }
    }
}

// ---------------- attention via mma.sync ----------------
// smem: Qs [256][80B], Ks [256][80B], Vt [32][528B], tab [961 float2]
#define AT_QS  0
#define AT_KS  20480
#define AT_VT  40960
#define AT_TAB 57856
#define ATTN_SMEM 65552

__global__ __launch_bounds__(256, 1) void attn_kernel(const float* __restrict__ x,
                                                      float* __restrict__ out)
{
    extern __shared__ char smc[];
    uint32_t sb = smem_u32(smc);
    float* tab = (float*)(smc + AT_TAB);
    int tid = threadIdx.x;
    int wid = tid >> 5, lane = tid & 31;
    int w = blockIdx.x >> 2, h = blockIdx.x & 3;
    size_t gbase = (size_t)(w * 4 + h) * (256 * 32);

    // paired pos table: tab[2t] = pos[t], tab[2t+1] = pos[t-1]
    for (int p = tid; p < POSN; p += 256) {
        float a = g_pos[h * POSN + p];
        tab[2 * p] = a;
        if (p < POSN - 1) tab[2 * p + 3] = a;
    }
    if (tid == 0) tab[1] = 0.f;

    // Qs/Ks: [256][40] bf16
    {
        const uint4* qsrc = (const uint4*)(g_q + gbase);
        const uint4* ksrc = (const uint4*)(g_k + gbase);
#pragma unroll
        for (int i = 0; i < 4; i++) {
            int c = i * 256 + tid;
            int n = c >> 2, ch = c & 3;
            *(uint4*)(smc + AT_QS + n * 80 + ch * 16) = qsrc[c];
            *(uint4*)(smc + AT_KS + n * 80 + ch * 16) = ksrc[c];
        }
    }
    // Vt: [32 d][264 tok] bf16 transpose
    {
        const uint4* vsrc = (const uint4*)(g_v + gbase);
#pragma unroll
        for (int i = 0; i < 2; i++) {
            int s = i * 256 + tid;
            int np = s >> 2, dg = s & 3;
            int n = np * 2;
            uint4 A = vsrc[n * 4 + dg];
            uint4 B = vsrc[(n + 1) * 4 + dg];
            uint32_t aw[4] = {A.x, A.y, A.z, A.w};
            uint32_t bw[4] = {B.x, B.y, B.z, B.w};
#pragma unroll
            for (int dd = 0; dd < 8; dd++) {
                uint32_t o32 = (dd & 1) ? __byte_perm(aw[dd >> 1], bw[dd >> 1], 0x7632)
                                        : __byte_perm(aw[dd >> 1], bw[dd >> 1], 0x5410);
                int d = dg * 8 + dd;
                *(uint32_t*)(smc + AT_VT + (d * 264 + n) * 2) = o32;
            }
        }
    }
    __syncthreads();

    int b_ = w >> 8, wh = (w >> 4) & 15, ww = w & 15;

    for (int p = 0; p < 2; p++) {
        int r0 = p * 128 + wid * 16;

        // ---- GEMM1: S[16][256] = Q @ K^T ----
        uint32_t af[2][4];
#pragma unroll
        for (int kt = 0; kt < 2; kt++) {
            uint32_t addr = sb + AT_QS
                + (r0 + (lane & 7) + ((lane >> 3) & 1) * 8) * 80
                + (kt * 16 + ((lane >> 3) >> 1) * 8) * 2;
            ldmx4(af[kt], addr);
        }
        float S[32][4];
#pragma unroll
        for (int nc = 0; nc < 32; nc++) {
            S[nc][0] = 0.f; S[nc][1] = 0.f; S[nc][2] = 0.f; S[nc][3] = 0.f;
            uint32_t bfr[4];
            uint32_t addr = sb + AT_KS + (nc * 8 + (lane & 7)) * 80 + (lane >> 3) * 16;
            ldmx4(bfr, addr);
            mma16816(S[nc], af[0], &bfr[0]);
            mma16816(S[nc], af[1], &bfr[2]);
        }

        // ---- bias from smem paired table + row max ----
        int row0 = r0 + (lane >> 2);
        int tbase = ((row0 >> 4) + 15) * 31 + (row0 & 15) + 15 - 2 * (lane & 3);
        float mx0 = -1e30f, mx1 = -1e30f;
#pragma unroll
        for (int nc = 0; nc < 32; nc++) {
            int tix = tbase - (nc >> 1) * 31 - 8 * (nc & 1);
            float2 b0 = *(const float2*)(tab + 2 * tix);
            float2 b1 = *(const float2*)(tab + 2 * tix + 16);
            S[nc][0] += b0.x; S[nc][1] += b0.y;
            S[nc][2] += b1.x; S[nc][3] += b1.y;
            mx0 = fmaxf(mx0, fmaxf(S[nc][0], S[nc][1]));
            mx1 = fmaxf(mx1, fmaxf(S[nc][2], S[nc][3]));
        }
        mx0 = fmaxf(mx0, __shfl_xor_sync(0xffffffffu, mx0, 1));
        mx0 = fmaxf(mx0, __shfl_xor_sync(0xffffffffu, mx0, 2));
        mx1 = fmaxf(mx1, __shfl_xor_sync(0xffffffffu, mx1, 1));
        mx1 = fmaxf(mx1, __shfl_xor_sync(0xffffffffu, mx1, 2));

        // ---- exp + pack P ----
        uint32_t paA[32], paB[32];
        float sum0 = 0.f, sum1 = 0.f;
#pragma unroll
        for (int nc = 0; nc < 32; nc++) {
            float e0 = ex2f(S[nc][0] - mx0);
            float e1 = ex2f(S[nc][1] - mx0);
            float e2 = ex2f(S[nc][2] - mx1);
            float e3 = ex2f(S[nc][3] - mx1);
            sum0 += e0 + e1; sum1 += e2 + e3;
            paA[nc] = bf2pack(e0, e1);
            paB[nc] = bf2pack(e2, e3);
        }
        sum0 += __shfl_xor_sync(0xffffffffu, sum0, 1);
        sum0 += __shfl_xor_sync(0xffffffffu, sum0, 2);
        sum1 += __shfl_xor_sync(0xffffffffu, sum1, 1);
        sum1 += __shfl_xor_sync(0xffffffffu, sum1, 2);
        float inv0, inv1;
        asm("rcp.approx.ftz.f32 %0,%1;" : "=f"(inv0) : "f"(sum0));
        asm("rcp.approx.ftz.f32 %0,%1;" : "=f"(inv1) : "f"(sum1));

        // ---- GEMM2: O[16][32] = P @ V ----
        float O[4][4];
#pragma unroll
        for (int nc2 = 0; nc2 < 4; nc2++) {
            O[nc2][0] = 0.f; O[nc2][1] = 0.f; O[nc2][2] = 0.f; O[nc2][3] = 0.f;
#pragma unroll
            for (int kg = 0; kg < 8; kg++) {
                uint32_t bfr[4];
                uint32_t addr = sb + AT_VT + (nc2 * 8 + (lane & 7)) * 528
                              + (kg * 32 + (lane >> 3) * 8) * 2;
                ldmx4(bfr, addr);
                uint32_t a0[4] = {paA[4 * kg],     paB[4 * kg],     paA[4 * kg + 1], paB[4 * kg + 1]};
                uint32_t a1[4] = {paA[4 * kg + 2], paB[4 * kg + 2], paA[4 * kg + 3], paB[4 * kg + 3]};
                mma16816(O[nc2], a0, &bfr[0]);
                mma16816(O[nc2], a1, &bfr[2]);
            }
        }

        // ---- epilogue ----
        int n0 = row0;
        int n1 = row0 + 8;
        int ir0 = (b_ << 16) + (((wh << 4) + (n0 >> 4)) << 8) + (ww << 4) + (n0 & 15);
        int ir1 = (b_ << 16) + (((wh << 4) + (n1 >> 4)) << 8) + (ww << 4) + (n1 & 15);
        const float* xr0 = x + (size_t)ir0 * 128 + h * 32;
        const float* xr1 = x + (size_t)ir1 * 128 + h * 32;
        float* or0 = out + (size_t)ir0 * 128 + h * 32;
        float* or1 = out + (size_t)ir1 * 128 + h * 32;
#pragma unroll
        for (int nc2 = 0; nc2 < 4; nc2++) {
            int d0 = nc2 * 8 + 2 * (lane & 3);
            float2 xv0 = *(const float2*)(xr0 + d0);
            float2 xv1 = *(const float2*)(xr1 + d0);
            float2 o0, o1;
            o0.x = O[nc2][0] * inv0 + xv0.x;
            o0.y = O[nc2][1] * inv0 + xv0.y;
            o1.x = O[nc2][2] * inv1 + xv1.x;
            o1.y = O[nc2][3] * inv1 + xv1.y;
            *(float2*)(or0 + d0) = o0;
            *(float2*)(or1 + d0) = o1;
        }
    }
}

// ---------------- launch ----------------
extern "C" void kernel_launch(void* const* d_in, const int* in_sizes, int n_in,
                              void* d_out, int out_size)
{
    (void)in_sizes; (void)n_in; (void)out_size;
    const float* x      = (const float*)d_in[0];
    const float* n1g    = (const float*)d_in[1];
    const float* n1b    = (const float*)d_in[2];
    const float* qkv_w  = (const float*)d_in[3];
    const float* qkv_b  = (const float*)d_in[4];
    const float* pp_w   = (const float*)d_in[5];
    const float* pp_b   = (const float*)d_in[6];
    const float* l1_g   = (const float*)d_in[7];
    const float* l1_b   = (const float*)d_in[8];
    const float* f1_w   = (const float*)d_in[9];
    const float* f1_b   = (const float*)d_in[10];
    const float* l2_g   = (const float*)d_in[11];
    const float* l2_b   = (const float*)d_in[12];
    const float* f2_w   = (const float*)d_in[13];
    const float* f2_b   = (const float*)d_in[14];
    const float* l3_g   = (const float*)d_in[15];
    const float* l3_b   = (const float*)d_in[16];
    const float* f3_w   = (const float*)d_in[17];
    const float* f3_b   = (const float*)d_in[18];
    float* out = (float*)d_out;

    cudaFuncSetAttribute(qkv_kernel,  cudaFuncAttributeMaxDynamicSharedMemorySize, QKV_SMEM);
    cudaFuncSetAttribute(attn_kernel, cudaFuncAttributeMaxDynamicSharedMemorySize, ATTN_SMEM);

    prep_pos_kernel<<<1, 1024>>>(pp_w, pp_b, l1_g, l1_b, f1_w, f1_b,
                                 l2_g, l2_b, f2_w, f2_b, l3_g, l3_b, f3_w, f3_b);
    prep_w_kernel<<<384, 128>>>(qkv_w, qkv_b, n1g, n1b);
    qkv_kernel<<<2048, 256, QKV_SMEM>>>(x);
    attn_kernel<<<2048, 256, ATTN_SMEM>>>(x, out);
}

// round 10
// speedup vs baseline: 5.1954x; 1.2573x over previous
#include <cuda_runtime.h>
#include <cuda_bf16.h>
#include <math.h>
#include <cstdint>

#define HEADS   4
#define NTOK    256
#define NWIN    512
#define POSN    961
#define QKSCALE 0.17677669529663689f
#define LOG2E   1.4426950408889634f

// ---------------- scratch ----------------
__device__ unsigned short g_q[NWIN * HEADS * NTOK * 32];
__device__ unsigned short g_k[NWIN * HEADS * NTOK * 32];
__device__ unsigned short g_v[NWIN * HEADS * NTOK * 32];
__device__ unsigned short g_wb[384 * 128];     // bf16 gamma-folded W, [j][k]
__device__ float g_cs[384];
__device__ float g_cb[384];
__device__ float g_pos[HEADS * POSN];          // pre-multiplied by LOG2E

// ---------------- helpers ----------------
__device__ __forceinline__ uint32_t bf2pack(float lo, float hi) {
    uint32_t r; asm("cvt.rn.bf16x2.f32 %0,%1,%2;" : "=r"(r) : "f"(hi), "f"(lo)); return r;
}
__device__ __forceinline__ uint32_t smem_u32(const void* p) {
    uint32_t a;
    asm("{ .reg .u64 t; cvta.to.shared.u64 t, %1; cvt.u32.u64 %0, t; }" : "=r"(a) : "l"(p));
    return a;
}
__device__ __forceinline__ void ldmx4(uint32_t* r, uint32_t addr) {
    asm volatile("ldmatrix.sync.aligned.m8n8.x4.shared.b16 {%0,%1,%2,%3}, [%4];"
        : "=r"(r[0]), "=r"(r[1]), "=r"(r[2]), "=r"(r[3]) : "r"(addr));
}
__device__ __forceinline__ void mma16816(float* c, const uint32_t* a, const uint32_t* b) {
    asm volatile("mma.sync.aligned.m16n8k16.row.col.f32.bf16.bf16.f32 "
        "{%0,%1,%2,%3},{%4,%5,%6,%7},{%8,%9},{%0,%1,%2,%3};"
        : "+f"(c[0]), "+f"(c[1]), "+f"(c[2]), "+f"(c[3])
        : "r"(a[0]), "r"(a[1]), "r"(a[2]), "r"(a[3]), "r"(b[0]), "r"(b[1]));
}
__device__ __forceinline__ float ex2f(float x) {
    float r; asm("ex2.approx.ftz.f32 %0,%1;" : "=f"(r) : "f"(x)); return r;
}

// ---------------- pos-bias MLP ----------------
__device__ __forceinline__ void ln_relu8(float* a, const float* g, const float* b) {
    float m = 0.f;
#pragma unroll
    for (int u = 0; u < 8; u++) m += a[u];
    m *= 0.125f;
    float v = 0.f;
#pragma unroll
    for (int u = 0; u < 8; u++) { float d = a[u] - m; v += d * d; }
    v *= 0.125f;
    float r = rsqrtf(v + 1e-5f);
#pragma unroll
    for (int u = 0; u < 8; u++) a[u] = fmaxf((a[u] - m) * r * g[u] + b[u], 0.f);
}
__device__ __forceinline__ void fc8(const float* a, float* y, const float* w, const float* b) {
#pragma unroll
    for (int o = 0; o < 8; o++) {
        float s = b[o];
#pragma unroll
        for (int u = 0; u < 8; u++) s += a[u] * w[o * 8 + u];
        y[o] = s;
    }
}

__global__ void prep_pos_kernel(
    const float* __restrict__ pp_w, const float* __restrict__ pp_b,
    const float* __restrict__ l1_g, const float* __restrict__ l1_b,
    const float* __restrict__ f1_w, const float* __restrict__ f1_b,
    const float* __restrict__ l2_g, const float* __restrict__ l2_b,
    const float* __restrict__ f2_w, const float* __restrict__ f2_b,
    const float* __restrict__ l3_g, const float* __restrict__ l3_b,
    const float* __restrict__ f3_w, const float* __restrict__ f3_b)
{
    int p = blockIdx.x * blockDim.x + threadIdx.x;
    if (p >= POSN) return;
    float bh = (float)(p / 31 - 15);
    float bw = (float)(p % 31 - 15);
    float a[8], y[8];
#pragma unroll
    for (int u = 0; u < 8; u++) a[u] = bh * pp_w[2 * u] + bw * pp_w[2 * u + 1] + pp_b[u];
    ln_relu8(a, l1_g, l1_b);
    fc8(a, y, f1_w, f1_b);
    ln_relu8(y, l2_g, l2_b);
    fc8(y, a, f2_w, f2_b);
    ln_relu8(a, l3_g, l3_b);
#pragma unroll
    for (int hh = 0; hh < HEADS; hh++) {
        float s = f3_b[hh];
#pragma unroll
        for (int u = 0; u < 8; u++) s += a[u] * f3_w[hh * 8 + u];
        g_pos[hh * POSN + p] = s * LOG2E;
    }
}

// ---------------- fold LN gamma into W, bf16 ----------------
__global__ void prep_w_kernel(const float* __restrict__ qkv_w, const float* __restrict__ qkv_b,
                              const float* __restrict__ g1, const float* __restrict__ b1)
{
    __shared__ float s1[128], s2[128];
    int j = blockIdx.x;
    int k = threadIdx.x;
    float w = qkv_w[j * 128 + k];
    float wg = w * g1[k];
    __nv_bfloat16 wbh = __float2bfloat16(wg);
    g_wb[j * 128 + k] = *(unsigned short*)&wbh;
    s1[k] = __bfloat162float(wbh);
    s2[k] = w * b1[k];
    __syncthreads();
    for (int o = 64; o > 0; o >>= 1) {
        if (k < o) { s1[k] += s1[k + o]; s2[k] += s2[k + o]; }
        __syncthreads();
    }
    if (k == 0) {
        float cb = s2[0] + qkv_b[j];
        if (j < 128) cb *= QKSCALE * LOG2E;
        g_cs[j] = s1[0];
        g_cb[j] = cb;
    }
}

// ---------------- QKV GEMM (128 rows x 384 cols per CTA, 512 threads) ----------------
#define QX_XB   0                       // 128 rows x 272B
#define QX_WB   34816                   // 384 rows x 272B
#define QX_CS   139264
#define QX_CB   140800
#define QX_MEAN 142336
#define QX_RSTD 142848
#define QKV_SMEM 143360

__global__ __launch_bounds__(512, 1) void qkv_kernel(const float* __restrict__ x)
{
    extern __shared__ char smc[];
    uint32_t sb = smem_u32(smc);
    float* scs   = (float*)(smc + QX_CS);
    float* scb   = (float*)(smc + QX_CB);
    float* smean = (float*)(smc + QX_MEAN);
    float* srstd = (float*)(smc + QX_RSTD);

    int tid = threadIdx.x;
    int wid = tid >> 5, lane = tid & 31;
    int t0 = blockIdx.x * 128;

    // stage Wb: 384 rows x 256B -> stride 272B
    {
        const uint4* src = (const uint4*)g_wb;
#pragma unroll
        for (int i = 0; i < 12; i++) {
            int f = i * 512 + tid;             // 6144 uint4
            int j = f >> 4, c = f & 15;
            *(uint4*)(smc + QX_WB + j * 272 + c * 16) = src[f];
        }
    }
    for (int p = tid; p < 384; p += 512) { scs[p] = g_cs[p]; scb[p] = g_cb[p]; }

    // load 128 x rows (4 threads per row), LN stats, bf16 convert
    {
        int row = tid >> 2, qtr = tid & 3;
        int t = t0 + row;
        int w = t >> 8, n = t & 255;
        int imgrow = ((w >> 8) << 16) + (((((w >> 4) & 15) << 4) + (n >> 4)) << 8)
                   + ((w & 15) << 4) + (n & 15);
        const float4* src4 = (const float4*)(x + (size_t)imgrow * 128 + qtr * 32);
        float s = 0.f, q = 0.f;
#pragma unroll
        for (int i = 0; i < 4; i++) {
            float4 a = src4[2 * i], b = src4[2 * i + 1];
            s += a.x + a.y + a.z + a.w + b.x + b.y + b.z + b.w;
            q += a.x*a.x + a.y*a.y + a.z*a.z + a.w*a.w + b.x*b.x + b.y*b.y + b.z*b.z + b.w*b.w;
            uint4 o;
            o.x = bf2pack(a.x, a.y); o.y = bf2pack(a.z, a.w);
            o.z = bf2pack(b.x, b.y); o.w = bf2pack(b.z, b.w);
            *(uint4*)(smc + QX_XB + row * 272 + qtr * 64 + i * 16) = o;
        }
        s += __shfl_xor_sync(0xffffffffu, s, 1);
        q += __shfl_xor_sync(0xffffffffu, q, 1);
        s += __shfl_xor_sync(0xffffffffu, s, 2);
        q += __shfl_xor_sync(0xffffffffu, q, 2);
        if ((lane & 3) == 0) {
            float mu = s * (1.f / 128.f);
            smean[row] = mu;
            srstd[row] = rsqrtf(q * (1.f / 128.f) - mu * mu + 1e-5f);
        }
    }
    __syncthreads();

    int rg = wid >> 2, cg = wid & 3;   // row-group (4x32), col-group (4x96)

    float c[2][12][4];
#pragma unroll
    for (int t = 0; t < 2; t++)
#pragma unroll
        for (int nj = 0; nj < 12; nj++) {
            c[t][nj][0] = 0.f; c[t][nj][1] = 0.f; c[t][nj][2] = 0.f; c[t][nj][3] = 0.f;
        }

    for (int kk = 0; kk < 4; kk++) {   // k32 chunks
        uint32_t af[2][2][4];
#pragma unroll
        for (int t = 0; t < 2; t++)
#pragma unroll
            for (int ks = 0; ks < 2; ks++) {
                uint32_t addr = sb + QX_XB
                    + (rg * 32 + t * 16 + (lane & 7) + ((lane >> 3) & 1) * 8) * 272
                    + (kk * 32 + ks * 16 + (lane >> 4) * 8) * 2;
                ldmx4(af[t][ks], addr);
            }
#pragma unroll
        for (int nj = 0; nj < 12; nj++) {
            uint32_t bfr[4];
            uint32_t addr = sb + QX_WB + (cg * 96 + nj * 8 + (lane & 7)) * 272
                          + (kk * 32 + (lane >> 3) * 8) * 2;
            ldmx4(bfr, addr);
            mma16816(c[0][nj], af[0][0], &bfr[0]);
            mma16816(c[0][nj], af[0][1], &bfr[2]);
            mma16816(c[1][nj], af[1][0], &bfr[0]);
            mma16816(c[1][nj], af[1][1], &bfr[2]);
        }
    }

    // epilogue
    float mn[2][2], rs[2][2];
#pragma unroll
    for (int t = 0; t < 2; t++) {
        int lr = rg * 32 + t * 16 + (lane >> 2);
        mn[t][0] = smean[lr];     mn[t][1] = smean[lr + 8];
        rs[t][0] = srstd[lr];     rs[t][1] = srstd[lr + 8];
    }
    int wv = blockIdx.x >> 1;
    int nloc0 = (blockIdx.x & 1) * 128 + rg * 32 + (lane >> 2);
#pragma unroll
    for (int nj = 0; nj < 12; nj++) {
        int j0 = cg * 96 + nj * 8 + 2 * (lane & 3);
        float2 cs2 = *(float2*)(scs + j0);
        float2 cb2 = *(float2*)(scb + j0);
        int head = (j0 >> 5) & 3;
        int d0 = j0 & 31;
        unsigned short* dst = (j0 < 128) ? g_q : (j0 < 256) ? g_k : g_v;
        float qsc = (j0 < 128) ? (QKSCALE * LOG2E) : 1.f;
#pragma unroll
        for (int t = 0; t < 2; t++) {
            float ia = rs[t][0] * qsc, ib = rs[t][1] * qsc;
            float v00 = ia * (c[t][nj][0] - mn[t][0] * cs2.x) + cb2.x;
            float v01 = ia * (c[t][nj][1] - mn[t][0] * cs2.y) + cb2.y;
            float v10 = ib * (c[t][nj][2] - mn[t][1] * cs2.x) + cb2.x;
            float v11 = ib * (c[t][nj][3] - mn[t][1] * cs2.y) + cb2.y;
            int n = nloc0 + t * 16;
            size_t o = ((size_t)(wv * 4 + head) * 256 + n) * 32 + d0;
            *(uint32_t*)(dst + o)          = bf2pack(v00, v01);
            *(uint32_t*)(dst + o + 8 * 32) = bf2pack(v10, v11);
        }
    }
}

// ---------------- attention via mma.sync (chunked softmax, 2 CTAs/SM) ----------------
// smem: Qs [256][80B], Ks [256][80B], Vt [32][528B], tab [961 float2]
#define AT_QS  0
#define AT_KS  20480
#define AT_VT  40960
#define AT_TAB 57856
#define ATTN_SMEM 65552

__global__ __launch_bounds__(256, 2) void attn_kernel(const float* __restrict__ x,
                                                      float* __restrict__ out)
{
    extern __shared__ char smc[];
    uint32_t sb = smem_u32(smc);
    float* tab = (float*)(smc + AT_TAB);
    int tid = threadIdx.x;
    int wid = tid >> 5, lane = tid & 31;
    int w = blockIdx.x >> 2, h = blockIdx.x & 3;
    size_t gbase = (size_t)(w * 4 + h) * (256 * 32);

    // paired pos table: tab[2t] = pos[t], tab[2t+1] = pos[t-1]
    for (int p = tid; p < POSN; p += 256) {
        float a = g_pos[h * POSN + p];
        tab[2 * p] = a;
        if (p < POSN - 1) tab[2 * p + 3] = a;
    }
    if (tid == 0) tab[1] = 0.f;

    // Qs/Ks: [256][40] bf16
    {
        const uint4* qsrc = (const uint4*)(g_q + gbase);
        const uint4* ksrc = (const uint4*)(g_k + gbase);
#pragma unroll
        for (int i = 0; i < 4; i++) {
            int c = i * 256 + tid;
            int n = c >> 2, ch = c & 3;
            *(uint4*)(smc + AT_QS + n * 80 + ch * 16) = qsrc[c];
            *(uint4*)(smc + AT_KS + n * 80 + ch * 16) = ksrc[c];
        }
    }
    // Vt: [32 d][264 tok] bf16 transpose
    {
        const uint4* vsrc = (const uint4*)(g_v + gbase);
#pragma unroll
        for (int i = 0; i < 2; i++) {
            int s = i * 256 + tid;
            int np = s >> 2, dg = s & 3;
            int n = np * 2;
            uint4 A = vsrc[n * 4 + dg];
            uint4 B = vsrc[(n + 1) * 4 + dg];
            uint32_t aw[4] = {A.x, A.y, A.z, A.w};
            uint32_t bw[4] = {B.x, B.y, B.z, B.w};
#pragma unroll
            for (int dd = 0; dd < 8; dd++) {
                uint32_t o32 = (dd & 1) ? __byte_perm(aw[dd >> 1], bw[dd >> 1], 0x7632)
                                        : __byte_perm(aw[dd >> 1], bw[dd >> 1], 0x5410);
                int d = dg * 8 + dd;
                *(uint32_t*)(smc + AT_VT + (d * 264 + n) * 2) = o32;
            }
        }
    }
    __syncthreads();

    int b_ = w >> 8, wh = (w >> 4) & 15, ww = w & 15;

    for (int p = 0; p < 2; p++) {
        int r0 = p * 128 + wid * 16;
        int row0 = r0 + (lane >> 2);
        int tbase = ((row0 >> 4) + 15) * 31 + (row0 & 15) + 15 - 2 * (lane & 3);

        // A frags (16 rows x k32)
        uint32_t af[2][4];
#pragma unroll
        for (int kt = 0; kt < 2; kt++) {
            uint32_t addr = sb + AT_QS
                + (r0 + (lane & 7) + ((lane >> 3) & 1) * 8) * 80
                + (kt * 16 + ((lane >> 3) >> 1) * 8) * 2;
            ldmx4(af[kt], addr);
        }

        float O[4][4];
#pragma unroll
        for (int nc2 = 0; nc2 < 4; nc2++) {
            O[nc2][0] = 0.f; O[nc2][1] = 0.f; O[nc2][2] = 0.f; O[nc2][3] = 0.f;
        }
        float sum0 = 0.f, sum1 = 0.f;

#pragma unroll
        for (int half = 0; half < 2; half++) {
            // ---- S chunk: 16 rows x 128 cols ----
            float S[16][4];
#pragma unroll
            for (int nc = 0; nc < 16; nc++) {
                S[nc][0] = 0.f; S[nc][1] = 0.f; S[nc][2] = 0.f; S[nc][3] = 0.f;
                uint32_t bfr[4];
                uint32_t addr = sb + AT_KS
                    + (half * 128 + nc * 8 + (lane & 7)) * 80 + (lane >> 3) * 16;
                ldmx4(bfr, addr);
                mma16816(S[nc], af[0], &bfr[0]);
                mma16816(S[nc], af[1], &bfr[2]);
            }

            // ---- bias + exp2 (no max shift; scores are O(1)) + pack ----
            uint32_t paA[16], paB[16];
#pragma unroll
            for (int nc = 0; nc < 16; nc++) {
                int g = half * 16 + nc;
                int tix = tbase - (g >> 1) * 31 - 8 * (g & 1);
                float2 b0 = *(const float2*)(tab + 2 * tix);
                float2 b1 = *(const float2*)(tab + 2 * tix + 16);
                float e0 = ex2f(S[nc][0] + b0.x);
                float e1 = ex2f(S[nc][1] + b0.y);
                float e2 = ex2f(S[nc][2] + b1.x);
                float e3 = ex2f(S[nc][3] + b1.y);
                sum0 += e0 + e1; sum1 += e2 + e3;
                paA[nc] = bf2pack(e0, e1);
                paB[nc] = bf2pack(e2, e3);
            }

            // ---- partial GEMM2 over this half's k-range ----
#pragma unroll
            for (int nc2 = 0; nc2 < 4; nc2++) {
#pragma unroll
                for (int kg = 0; kg < 4; kg++) {
                    uint32_t bfr[4];
                    uint32_t addr = sb + AT_VT + (nc2 * 8 + (lane & 7)) * 528
                                  + (half * 128 + kg * 32 + (lane >> 3) * 8) * 2;
                    ldmx4(bfr, addr);
                    uint32_t a0[4] = {paA[4 * kg],     paB[4 * kg],     paA[4 * kg + 1], paB[4 * kg + 1]};
                    uint32_t a1[4] = {paA[4 * kg + 2], paB[4 * kg + 2], paA[4 * kg + 3], paB[4 * kg + 3]};
                    mma16816(O[nc2], a0, &bfr[0]);
                    mma16816(O[nc2], a1, &bfr[2]);
                }
            }
        }

        // ---- reduce sums across quad ----
        sum0 += __shfl_xor_sync(0xffffffffu, sum0, 1);
        sum0 += __shfl_xor_sync(0xffffffffu, sum0, 2);
        sum1 += __shfl_xor_sync(0xffffffffu, sum1, 1);
        sum1 += __shfl_xor_sync(0xffffffffu, sum1, 2);
        float inv0, inv1;
        asm("rcp.approx.ftz.f32 %0,%1;" : "=f"(inv0) : "f"(sum0));
        asm("rcp.approx.ftz.f32 %0,%1;" : "=f"(inv1) : "f"(sum1));

        // ---- epilogue ----
        int n0 = row0;
        int n1 = row0 + 8;
        int ir0 = (b_ << 16) + (((wh << 4) + (n0 >> 4)) << 8) + (ww << 4) + (n0 & 15);
        int ir1 = (b_ << 16) + (((wh << 4) + (n1 >> 4)) << 8) + (ww << 4) + (n1 & 15);
        const float* xr0 = x + (size_t)ir0 * 128 + h * 32;
        const float* xr1 = x + (size_t)ir1 * 128 + h * 32;
        float* or0 = out + (size_t)ir0 * 128 + h * 32;
        float* or1 = out + (size_t)ir1 * 128 + h * 32;
#pragma unroll
        for (int nc2 = 0; nc2 < 4; nc2++) {
            int d0 = nc2 * 8 + 2 * (lane & 3);
            float2 xv0 = *(const float2*)(xr0 + d0);
            float2 xv1 = *(const float2*)(xr1 + d0);
            float2 o0, o1;
            o0.x = O[nc2][0] * inv0 + xv0.x;
            o0.y = O[nc2][1] * inv0 + xv0.y;
            o1.x = O[nc2][2] * inv1 + xv1.x;
            o1.y = O[nc2][3] * inv1 + xv1.y;
            *(float2*)(or0 + d0) = o0;
            *(float2*)(or1 + d0) = o1;
        }
    }
}

// ---------------- launch ----------------
extern "C" void kernel_launch(void* const* d_in, const int* in_sizes, int n_in,
                              void* d_out, int out_size)
{
    (void)in_sizes; (void)n_in; (void)out_size;
    const float* x      = (const float*)d_in[0];
    const float* n1g    = (const float*)d_in[1];
    const float* n1b    = (const float*)d_in[2];
    const float* qkv_w  = (const float*)d_in[3];
    const float* qkv_b  = (const float*)d_in[4];
    const float* pp_w   = (const float*)d_in[5];
    const float* pp_b   = (const float*)d_in[6];
    const float* l1_g   = (const float*)d_in[7];
    const float* l1_b   = (const float*)d_in[8];
    const float* f1_w   = (const float*)d_in[9];
    const float* f1_b   = (const float*)d_in[10];
    const float* l2_g   = (const float*)d_in[11];
    const float* l2_b   = (const float*)d_in[12];
    const float* f2_w   = (const float*)d_in[13];
    const float* f2_b   = (const float*)d_in[14];
    const float* l3_g   = (const float*)d_in[15];
    const float* l3_b   = (const float*)d_in[16];
    const float* f3_w   = (const float*)d_in[17];
    const float* f3_b   = (const float*)d_in[18];
    float* out = (float*)d_out;

    cudaFuncSetAttribute(qkv_kernel,  cudaFuncAttributeMaxDynamicSharedMemorySize, QKV_SMEM);
    cudaFuncSetAttribute(attn_kernel, cudaFuncAttributeMaxDynamicSharedMemorySize, ATTN_SMEM);

    prep_pos_kernel<<<1, 1024>>>(pp_w, pp_b, l1_g, l1_b, f1_w, f1_b,
                                 l2_g, l2_b, f2_w, f2_b, l3_g, l3_b, f3_w, f3_b);
    prep_w_kernel<<<384, 128>>>(qkv_w, qkv_b, n1g, n1b);
    qkv_kernel<<<1024, 512, QKV_SMEM>>>(x);
    attn_kernel<<<2048, 256, ATTN_SMEM>>>(x, out);
}

// round 12
// speedup vs baseline: 5.4381x; 1.0467x over previous
#include <cuda_runtime.h>
#include <cuda_bf16.h>
#include <math.h>
#include <cstdint>

#define HEADS   4
#define NTOK    256
#define NWIN    512
#define POSN    961
#define QKSCALE 0.17677669529663689f
#define LOG2E   1.4426950408889634f

// ---------------- scratch ----------------
__device__ unsigned short g_q[NWIN * HEADS * NTOK * 32];
__device__ unsigned short g_k[NWIN * HEADS * NTOK * 32];
__device__ unsigned short g_v[NWIN * HEADS * NTOK * 32];
__device__ unsigned short g_wb[384 * 128];     // bf16 gamma-folded W, [j][k]
__device__ float g_cs[384];
__device__ float g_cb[384];
__device__ float g_pos[HEADS * POSN];          // pre-multiplied by LOG2E

// ---------------- helpers ----------------
__device__ __forceinline__ uint32_t bf2pack(float lo, float hi) {
    uint32_t r; asm("cvt.rn.bf16x2.f32 %0,%1,%2;" : "=r"(r) : "f"(hi), "f"(lo)); return r;
}
__device__ __forceinline__ uint32_t smem_u32(const void* p) {
    uint32_t a;
    asm("{ .reg .u64 t; cvta.to.shared.u64 t, %1; cvt.u32.u64 %0, t; }" : "=r"(a) : "l"(p));
    return a;
}
__device__ __forceinline__ void ldmx4(uint32_t* r, uint32_t addr) {
    asm volatile("ldmatrix.sync.aligned.m8n8.x4.shared.b16 {%0,%1,%2,%3}, [%4];"
        : "=r"(r[0]), "=r"(r[1]), "=r"(r[2]), "=r"(r[3]) : "r"(addr));
}
__device__ __forceinline__ void mma16816(float* c, const uint32_t* a, const uint32_t* b) {
    asm volatile("mma.sync.aligned.m16n8k16.row.col.f32.bf16.bf16.f32 "
        "{%0,%1,%2,%3},{%4,%5,%6,%7},{%8,%9},{%0,%1,%2,%3};"
        : "+f"(c[0]), "+f"(c[1]), "+f"(c[2]), "+f"(c[3])
        : "r"(a[0]), "r"(a[1]), "r"(a[2]), "r"(a[3]), "r"(b[0]), "r"(b[1]));
}
__device__ __forceinline__ float ex2f(float x) {
    float r; asm("ex2.approx.ftz.f32 %0,%1;" : "=f"(r) : "f"(x)); return r;
}

// ---------------- pos-bias MLP ----------------
__device__ __forceinline__ void ln_relu8(float* a, const float* g, const float* b) {
    float m = 0.f;
#pragma unroll
    for (int u = 0; u < 8; u++) m += a[u];
    m *= 0.125f;
    float v = 0.f;
#pragma unroll
    for (int u = 0; u < 8; u++) { float d = a[u] - m; v += d * d; }
    v *= 0.125f;
    float r = rsqrtf(v + 1e-5f);
#pragma unroll
    for (int u = 0; u < 8; u++) a[u] = fmaxf((a[u] - m) * r * g[u] + b[u], 0.f);
}
__device__ __forceinline__ void fc8(const float* a, float* y, const float* w, const float* b) {
#pragma unroll
    for (int o = 0; o < 8; o++) {
        float s = b[o];
#pragma unroll
        for (int u = 0; u < 8; u++) s += a[u] * w[o * 8 + u];
        y[o] = s;
    }
}

__global__ void prep_pos_kernel(
    const float* __restrict__ pp_w, const float* __restrict__ pp_b,
    const float* __restrict__ l1_g, const float* __restrict__ l1_b,
    const float* __restrict__ f1_w, const float* __restrict__ f1_b,
    const float* __restrict__ l2_g, const float* __restrict__ l2_b,
    const float* __restrict__ f2_w, const float* __restrict__ f2_b,
    const float* __restrict__ l3_g, const float* __restrict__ l3_b,
    const float* __restrict__ f3_w, const float* __restrict__ f3_b)
{
    int p = blockIdx.x * blockDim.x + threadIdx.x;
    if (p >= POSN) return;
    float bh = (float)(p / 31 - 15);
    float bw = (float)(p % 31 - 15);
    float a[8], y[8];
#pragma unroll
    for (int u = 0; u < 8; u++) a[u] = bh * pp_w[2 * u] + bw * pp_w[2 * u + 1] + pp_b[u];
    ln_relu8(a, l1_g, l1_b);
    fc8(a, y, f1_w, f1_b);
    ln_relu8(y, l2_g, l2_b);
    fc8(y, a, f2_w, f2_b);
    ln_relu8(a, l3_g, l3_b);
#pragma unroll
    for (int hh = 0; hh < HEADS; hh++) {
        float s = f3_b[hh];
#pragma unroll
        for (int u = 0; u < 8; u++) s += a[u] * f3_w[hh * 8 + u];
        g_pos[hh * POSN + p] = s * LOG2E;
    }
}

// ---------------- fold LN gamma into W, bf16 ----------------
__global__ void prep_w_kernel(const float* __restrict__ qkv_w, const float* __restrict__ qkv_b,
                              const float* __restrict__ g1, const float* __restrict__ b1)
{
    __shared__ float s1[128], s2[128];
    int j = blockIdx.x;
    int k = threadIdx.x;
    float w = qkv_w[j * 128 + k];
    float wg = w * g1[k];
    __nv_bfloat16 wbh = __float2bfloat16(wg);
    g_wb[j * 128 + k] = *(unsigned short*)&wbh;
    s1[k] = __bfloat162float(wbh);
    s2[k] = w * b1[k];
    __syncthreads();
    for (int o = 64; o > 0; o >>= 1) {
        if (k < o) { s1[k] += s1[k + o]; s2[k] += s2[k + o]; }
        __syncthreads();
    }
    if (k == 0) {
        float cb = s2[0] + qkv_b[j];
        if (j < 128) cb *= QKSCALE * LOG2E;
        g_cs[j] = s1[0];
        g_cb[j] = cb;
    }
}

// ---------------- QKV GEMM (128 rows x 384 cols per CTA, 512 threads) ----------------
#define QX_XB   0                       // 128 rows x 272B
#define QX_WB   34816                   // 384 rows x 272B
#define QX_CS   139264
#define QX_CB   140800
#define QX_MEAN 142336
#define QX_RSTD 142848
#define QKV_SMEM 143360

__global__ __launch_bounds__(512, 1) void qkv_kernel(const float* __restrict__ x)
{
    extern __shared__ char smc[];
    uint32_t sb = smem_u32(smc);
    float* scs   = (float*)(smc + QX_CS);
    float* scb   = (float*)(smc + QX_CB);
    float* smean = (float*)(smc + QX_MEAN);
    float* srstd = (float*)(smc + QX_RSTD);

    int tid = threadIdx.x;
    int wid = tid >> 5, lane = tid & 31;
    int t0 = blockIdx.x * 128;

    {
        const uint4* src = (const uint4*)g_wb;
#pragma unroll
        for (int i = 0; i < 12; i++) {
            int f = i * 512 + tid;
            int j = f >> 4, c = f & 15;
            *(uint4*)(smc + QX_WB + j * 272 + c * 16) = src[f];
        }
    }
    for (int p = tid; p < 384; p += 512) { scs[p] = g_cs[p]; scb[p] = g_cb[p]; }

    {
        int row = tid >> 2, qtr = tid & 3;
        int t = t0 + row;
        int w = t >> 8, n = t & 255;
        int imgrow = ((w >> 8) << 16) + (((((w >> 4) & 15) << 4) + (n >> 4)) << 8)
                   + ((w & 15) << 4) + (n & 15);
        const float4* src4 = (const float4*)(x + (size_t)imgrow * 128 + qtr * 32);
        float s = 0.f, q = 0.f;
#pragma unroll
        for (int i = 0; i < 4; i++) {
            float4 a = src4[2 * i], b = src4[2 * i + 1];
            s += a.x + a.y + a.z + a.w + b.x + b.y + b.z + b.w;
            q += a.x*a.x + a.y*a.y + a.z*a.z + a.w*a.w + b.x*b.x + b.y*b.y + b.z*b.z + b.w*b.w;
            uint4 o;
            o.x = bf2pack(a.x, a.y); o.y = bf2pack(a.z, a.w);
            o.z = bf2pack(b.x, b.y); o.w = bf2pack(b.z, b.w);
            *(uint4*)(smc + QX_XB + row * 272 + qtr * 64 + i * 16) = o;
        }
        s += __shfl_xor_sync(0xffffffffu, s, 1);
        q += __shfl_xor_sync(0xffffffffu, q, 1);
        s += __shfl_xor_sync(0xffffffffu, s, 2);
        q += __shfl_xor_sync(0xffffffffu, q, 2);
        if ((lane & 3) == 0) {
            float mu = s * (1.f / 128.f);
            smean[row] = mu;
            srstd[row] = rsqrtf(q * (1.f / 128.f) - mu * mu + 1e-5f);
        }
    }
    __syncthreads();

    int rg = wid >> 2, cg = wid & 3;

    float c[2][12][4];
#pragma unroll
    for (int t = 0; t < 2; t++)
#pragma unroll
        for (int nj = 0; nj < 12; nj++) {
            c[t][nj][0] = 0.f; c[t][nj][1] = 0.f; c[t][nj][2] = 0.f; c[t][nj][3] = 0.f;
        }

    for (int kk = 0; kk < 4; kk++) {
        uint32_t af[2][2][4];
#pragma unroll
        for (int t = 0; t < 2; t++)
#pragma unroll
            for (int ks = 0; ks < 2; ks++) {
                uint32_t addr = sb + QX_XB
                    + (rg * 32 + t * 16 + (lane & 7) + ((lane >> 3) & 1) * 8) * 272
                    + (kk * 32 + ks * 16 + (lane >> 4) * 8) * 2;
                ldmx4(af[t][ks], addr);
            }
#pragma unroll
        for (int nj = 0; nj < 12; nj++) {
            uint32_t bfr[4];
            uint32_t addr = sb + QX_WB + (cg * 96 + nj * 8 + (lane & 7)) * 272
                          + (kk * 32 + (lane >> 3) * 8) * 2;
            ldmx4(bfr, addr);
            mma16816(c[0][nj], af[0][0], &bfr[0]);
            mma16816(c[0][nj], af[0][1], &bfr[2]);
            mma16816(c[1][nj], af[1][0], &bfr[0]);
            mma16816(c[1][nj], af[1][1], &bfr[2]);
        }
    }

    float mn[2][2], rs[2][2];
#pragma unroll
    for (int t = 0; t < 2; t++) {
        int lr = rg * 32 + t * 16 + (lane >> 2);
        mn[t][0] = smean[lr];     mn[t][1] = smean[lr + 8];
        rs[t][0] = srstd[lr];     rs[t][1] = srstd[lr + 8];
    }
    int wv = blockIdx.x >> 1;
    int nloc0 = (blockIdx.x & 1) * 128 + rg * 32 + (lane >> 2);
#pragma unroll
    for (int nj = 0; nj < 12; nj++) {
        int j0 = cg * 96 + nj * 8 + 2 * (lane & 3);
        float2 cs2 = *(float2*)(scs + j0);
        float2 cb2 = *(float2*)(scb + j0);
        int head = (j0 >> 5) & 3;
        int d0 = j0 & 31;
        unsigned short* dst = (j0 < 128) ? g_q : (j0 < 256) ? g_k : g_v;
        float qsc = (j0 < 128) ? (QKSCALE * LOG2E) : 1.f;
#pragma unroll
        for (int t = 0; t < 2; t++) {
            float ia = rs[t][0] * qsc, ib = rs[t][1] * qsc;
            float v00 = ia * (c[t][nj][0] - mn[t][0] * cs2.x) + cb2.x;
            float v01 = ia * (c[t][nj][1] - mn[t][0] * cs2.y) + cb2.y;
            float v10 = ib * (c[t][nj][2] - mn[t][1] * cs2.x) + cb2.x;
            float v11 = ib * (c[t][nj][3] - mn[t][1] * cs2.y) + cb2.y;
            int n = nloc0 + t * 16;
            size_t o = ((size_t)(wv * 4 + head) * 256 + n) * 32 + d0;
            *(uint32_t*)(dst + o)          = bf2pack(v00, v01);
            *(uint32_t*)(dst + o + 8 * 32) = bf2pack(v10, v11);
        }
    }
}

// ---------------- attention: single-pass, 32 rows/warp, 8x32-col chunks ----------------
#define AT_QS  0
#define AT_KS  20480
#define AT_VT  40960
#define AT_TAB 57856
#define ATTN_SMEM 65552

__global__ __launch_bounds__(256, 2) void attn_kernel(const float* __restrict__ x,
                                                      float* __restrict__ out)
{
    extern __shared__ char smc[];
    uint32_t sb = smem_u32(smc);
    float* tab = (float*)(smc + AT_TAB);
    int tid = threadIdx.x;
    int wid = tid >> 5, lane = tid & 31;
    int w = blockIdx.x >> 2, h = blockIdx.x & 3;
    size_t gbase = (size_t)(w * 4 + h) * (256 * 32);

    // paired pos table: tab[2t] = pos[t], tab[2t+1] = pos[t-1]
    for (int p = tid; p < POSN; p += 256) {
        float a = g_pos[h * POSN + p];
        tab[2 * p] = a;
        if (p < POSN - 1) tab[2 * p + 3] = a;
    }
    if (tid == 0) tab[1] = 0.f;

    // Qs/Ks: [256][40] bf16
    {
        const uint4* qsrc = (const uint4*)(g_q + gbase);
        const uint4* ksrc = (const uint4*)(g_k + gbase);
#pragma unroll
        for (int i = 0; i < 4; i++) {
            int c = i * 256 + tid;
            int n = c >> 2, ch = c & 3;
            *(uint4*)(smc + AT_QS + n * 80 + ch * 16) = qsrc[c];
            *(uint4*)(smc + AT_KS + n * 80 + ch * 16) = ksrc[c];
        }
    }
    // Vt: [32 d][264 tok] bf16 transpose
    {
        const uint4* vsrc = (const uint4*)(g_v + gbase);
#pragma unroll
        for (int i = 0; i < 2; i++) {
            int s = i * 256 + tid;
            int np = s >> 2, dg = s & 3;
            int n = np * 2;
            uint4 A = vsrc[n * 4 + dg];
            uint4 B = vsrc[(n + 1) * 4 + dg];
            uint32_t aw[4] = {A.x, A.y, A.z, A.w};
            uint32_t bw[4] = {B.x, B.y, B.z, B.w};
#pragma unroll
            for (int dd = 0; dd < 8; dd++) {
                uint32_t o32 = (dd & 1) ? __byte_perm(aw[dd >> 1], bw[dd >> 1], 0x7632)
                                        : __byte_perm(aw[dd >> 1], bw[dd >> 1], 0x5410);
                int d = dg * 8 + dd;
                *(uint32_t*)(smc + AT_VT + (d * 264 + n) * 2) = o32;
            }
        }
    }
    __syncthreads();

    int b_ = w >> 8, wh = (w >> 4) & 15, ww = w & 15;
    int r0 = wid * 32;                         // this warp's 32 rows
    int row0 = r0 + (lane >> 2);
    // tab base for row0 (cols offset folded later); rows +8,+16,+24 are +8,+31,+39
    int tb0 = ((row0 >> 4) + 15) * 31 + (row0 & 15) + 15 - 2 * (lane & 3);

    // Q A-frags: [m-tile][k16] loaded once
    uint32_t af[2][2][4];
#pragma unroll
    for (int m = 0; m < 2; m++)
#pragma unroll
        for (int kt = 0; kt < 2; kt++) {
            uint32_t addr = sb + AT_QS
                + (r0 + m * 16 + (lane & 7) + ((lane >> 3) & 1) * 8) * 80
                + (kt * 16 + ((lane >> 3) >> 1) * 8) * 2;
            ldmx4(af[m][kt], addr);
        }

    float O[2][4][4];
#pragma unroll
    for (int m = 0; m < 2; m++)
#pragma unroll
        for (int nc2 = 0; nc2 < 4; nc2++) {
            O[m][nc2][0] = 0.f; O[m][nc2][1] = 0.f; O[m][nc2][2] = 0.f; O[m][nc2][3] = 0.f;
        }
    float sum00 = 0.f, sum01 = 0.f, sum10 = 0.f, sum11 = 0.f;

#pragma unroll
    for (int chunk = 0; chunk < 8; chunk++) {
        // ---- GEMM1 chunk: S[2 m][4 nc][4] over 32 cols ----
        float S[2][4][4];
#pragma unroll
        for (int nc = 0; nc < 4; nc++) {
            S[0][nc][0] = 0.f; S[0][nc][1] = 0.f; S[0][nc][2] = 0.f; S[0][nc][3] = 0.f;
            S[1][nc][0] = 0.f; S[1][nc][1] = 0.f; S[1][nc][2] = 0.f; S[1][nc][3] = 0.f;
            uint32_t bfr[4];
            uint32_t addr = sb + AT_KS
                + ((chunk * 4 + nc) * 8 + (lane & 7)) * 80 + (lane >> 3) * 16;
            ldmx4(bfr, addr);
            mma16816(S[0][nc], af[0][0], &bfr[0]);
            mma16816(S[0][nc], af[0][1], &bfr[2]);
            mma16816(S[1][nc], af[1][0], &bfr[0]);
            mma16816(S[1][nc], af[1][1], &bfr[2]);
        }

        // ---- bias + exp2 + pack (rows r, r+8 | r+16, r+24) ----
        uint32_t paA0[4], paB0[4], paA1[4], paB1[4];
#pragma unroll
        for (int nc = 0; nc < 4; nc++) {
            int g = chunk * 4 + nc;
            int t00 = tb0 - (g >> 1) * 31 - 8 * (g & 1);
            float2 b00 = *(const float2*)(tab + 2 * t00);
            float2 b08 = *(const float2*)(tab + 2 * t00 + 16);
            float2 b16 = *(const float2*)(tab + 2 * t00 + 62);
            float2 b24 = *(const float2*)(tab + 2 * t00 + 78);
            float e0 = ex2f(S[0][nc][0] + b00.x);
            float e1 = ex2f(S[0][nc][1] + b00.y);
            float e2 = ex2f(S[0][nc][2] + b08.x);
            float e3 = ex2f(S[0][nc][3] + b08.y);
            float f0 = ex2f(S[1][nc][0] + b16.x);
            float f1 = ex2f(S[1][nc][1] + b16.y);
            float f2 = ex2f(S[1][nc][2] + b24.x);
            float f3 = ex2f(S[1][nc][3] + b24.y);
            sum00 += e0 + e1; sum01 += e2 + e3;
            sum10 += f0 + f1; sum11 += f2 + f3;
            paA0[nc] = bf2pack(e0, e1);
            paB0[nc] = bf2pack(e2, e3);
            paA1[nc] = bf2pack(f0, f1);
            paB1[nc] = bf2pack(f2, f3);
        }

        // ---- partial GEMM2 over this chunk's k32 ----
        uint32_t a00[4] = {paA0[0], paB0[0], paA0[1], paB0[1]};
        uint32_t a01[4] = {paA0[2], paB0[2], paA0[3], paB0[3]};
        uint32_t a10[4] = {paA1[0], paB1[0], paA1[1], paB1[1]};
        uint32_t a11[4] = {paA1[2], paB1[2], paA1[3], paB1[3]};
#pragma unroll
        for (int nc2 = 0; nc2 < 4; nc2++) {
            uint32_t vfr[4];
            uint32_t addr = sb + AT_VT + (nc2 * 8 + (lane & 7)) * 528
                          + (chunk * 32 + (lane >> 3) * 8) * 2;
            ldmx4(vfr, addr);
            mma16816(O[0][nc2], a00, &vfr[0]);
            mma16816(O[0][nc2], a01, &vfr[2]);
            mma16816(O[1][nc2], a10, &vfr[0]);
            mma16816(O[1][nc2], a11, &vfr[2]);
        }
    }

    // ---- quad-reduce sums ----
    sum00 += __shfl_xor_sync(0xffffffffu, sum00, 1);
    sum00 += __shfl_xor_sync(0xffffffffu, sum00, 2);
    sum01 += __shfl_xor_sync(0xffffffffu, sum01, 1);
    sum01 += __shfl_xor_sync(0xffffffffu, sum01, 2);
    sum10 += __shfl_xor_sync(0xffffffffu, sum10, 1);
    sum10 += __shfl_xor_sync(0xffffffffu, sum10, 2);
    sum11 += __shfl_xor_sync(0xffffffffu, sum11, 1);
    sum11 += __shfl_xor_sync(0xffffffffu, sum11, 2);
    float inv[2][2];
    asm("rcp.approx.ftz.f32 %0,%1;" : "=f"(inv[0][0]) : "f"(sum00));
    asm("rcp.approx.ftz.f32 %0,%1;" : "=f"(inv[0][1]) : "f"(sum01));
    asm("rcp.approx.ftz.f32 %0,%1;" : "=f"(inv[1][0]) : "f"(sum10));
    asm("rcp.approx.ftz.f32 %0,%1;" : "=f"(inv[1][1]) : "f"(sum11));

    // ---- epilogue ----
#pragma unroll
    for (int m = 0; m < 2; m++) {
        int n0 = row0 + m * 16;
        int n1 = n0 + 8;
        int ir0 = (b_ << 16) + (((wh << 4) + (n0 >> 4)) << 8) + (ww << 4) + (n0 & 15);
        int ir1 = (b_ << 16) + (((wh << 4) + (n1 >> 4)) << 8) + (ww << 4) + (n1 & 15);
        const float* xr0 = x + (size_t)ir0 * 128 + h * 32;
        const float* xr1 = x + (size_t)ir1 * 128 + h * 32;
        float* or0 = out + (size_t)ir0 * 128 + h * 32;
        float* or1 = out + (size_t)ir1 * 128 + h * 32;
#pragma unroll
        for (int nc2 = 0; nc2 < 4; nc2++) {
            int d0 = nc2 * 8 + 2 * (lane & 3);
            float2 xv0 = *(const float2*)(xr0 + d0);
            float2 xv1 = *(const float2*)(xr1 + d0);
            float2 o0, o1;
            o0.x = O[m][nc2][0] * inv[m][0] + xv0.x;
            o0.y = O[m][nc2][1] * inv[m][0] + xv0.y;
            o1.x = O[m][nc2][2] * inv[m][1] + xv1.x;
            o1.y = O[m][nc2][3] * inv[m][1] + xv1.y;
            *(float2*)(or0 + d0) = o0;
            *(float2*)(or1 + d0) = o1;
        }
    }
}

// ---------------- launch ----------------
extern "C" void kernel_launch(void* const* d_in, const int* in_sizes, int n_in,
                              void* d_out, int out_size)
{
    (void)in_sizes; (void)n_in; (void)out_size;
    const float* x      = (const float*)d_in[0];
    const float* n1g    = (const float*)d_in[1];
    const float* n1b    = (const float*)d_in[2];
    const float* qkv_w  = (const float*)d_in[3];
    const float* qkv_b  = (const float*)d_in[4];
    const float* pp_w   = (const float*)d_in[5];
    const float* pp_b   = (const float*)d_in[6];
    const float* l1_g   = (const float*)d_in[7];
    const float* l1_b   = (const float*)d_in[8];
    const float* f1_w   = (const float*)d_in[9];
    const float* f1_b   = (const float*)d_in[10];
    const float* l2_g   = (const float*)d_in[11];
    const float* l2_b   = (const float*)d_in[12];
    const float* f2_w   = (const float*)d_in[13];
    const float* f2_b   = (const float*)d_in[14];
    const float* l3_g   = (const float*)d_in[15];
    const float* l3_b   = (const float*)d_in[16];
    const float* f3_w   = (const float*)d_in[17];
    const float* f3_b   = (const float*)d_in[18];
    float* out = (float*)d_out;

    cudaFuncSetAttribute(qkv_kernel,  cudaFuncAttributeMaxDynamicSharedMemorySize, QKV_SMEM);
    cudaFuncSetAttribute(attn_kernel, cudaFuncAttributeMaxDynamicSharedMemorySize, ATTN_SMEM);

    prep_pos_kernel<<<1, 1024>>>(pp_w, pp_b, l1_g, l1_b, f1_w, f1_b,
                                 l2_g, l2_b, f2_w, f2_b, l3_g, l3_b, f3_w, f3_b);
    prep_w_kernel<<<384, 128>>>(qkv_w, qkv_b, n1g, n1b);
    qkv_kernel<<<1024, 512, QKV_SMEM>>>(x);
    attn_kernel<<<2048, 256, ATTN_SMEM>>>(x, out);
}

// round 14
// speedup vs baseline: 5.4975x; 1.0109x over previous
#include <cuda_runtime.h>
#include <cuda_bf16.h>
#include <math.h>
#include <cstdint>

#define HEADS   4
#define NTOK    256
#define NWIN    512
#define POSN    961
#define QKSCALE 0.17677669529663689f
#define LOG2E   1.4426950408889634f

// ---------------- scratch ----------------
__device__ unsigned short g_q[NWIN * HEADS * NTOK * 32];
__device__ unsigned short g_k[NWIN * HEADS * NTOK * 32];
__device__ unsigned short g_v[NWIN * HEADS * NTOK * 32];
__device__ unsigned short g_wb[384 * 128];     // bf16 gamma-folded W, [j][k]
__device__ float g_cs[384];
__device__ float g_cb[384];
__device__ float g_pos[HEADS * POSN];          // pre-multiplied by LOG2E

// ---------------- helpers ----------------
__device__ __forceinline__ uint32_t bf2pack(float lo, float hi) {
    uint32_t r; asm("cvt.rn.bf16x2.f32 %0,%1,%2;" : "=r"(r) : "f"(hi), "f"(lo)); return r;
}
__device__ __forceinline__ uint32_t smem_u32(const void* p) {
    uint32_t a;
    asm("{ .reg .u64 t; cvta.to.shared.u64 t, %1; cvt.u32.u64 %0, t; }" : "=r"(a) : "l"(p));
    return a;
}
__device__ __forceinline__ void ldmx4(uint32_t* r, uint32_t addr) {
    asm volatile("ldmatrix.sync.aligned.m8n8.x4.shared.b16 {%0,%1,%2,%3}, [%4];"
        : "=r"(r[0]), "=r"(r[1]), "=r"(r[2]), "=r"(r[3]) : "r"(addr));
}
__device__ __forceinline__ void ldmx4t(uint32_t* r, uint32_t addr) {
    asm volatile("ldmatrix.sync.aligned.m8n8.x4.trans.shared.b16 {%0,%1,%2,%3}, [%4];"
        : "=r"(r[0]), "=r"(r[1]), "=r"(r[2]), "=r"(r[3]) : "r"(addr));
}
__device__ __forceinline__ void mma16816(float* c, const uint32_t* a, const uint32_t* b) {
    asm volatile("mma.sync.aligned.m16n8k16.row.col.f32.bf16.bf16.f32 "
        "{%0,%1,%2,%3},{%4,%5,%6,%7},{%8,%9},{%0,%1,%2,%3};"
        : "+f"(c[0]), "+f"(c[1]), "+f"(c[2]), "+f"(c[3])
        : "r"(a[0]), "r"(a[1]), "r"(a[2]), "r"(a[3]), "r"(b[0]), "r"(b[1]));
}
__device__ __forceinline__ float ex2f(float x) {
    float r; asm("ex2.approx.ftz.f32 %0,%1;" : "=f"(r) : "f"(x)); return r;
}

// ---------------- pos-bias MLP ----------------
__device__ __forceinline__ void ln_relu8(float* a, const float* g, const float* b) {
    float m = 0.f;
#pragma unroll
    for (int u = 0; u < 8; u++) m += a[u];
    m *= 0.125f;
    float v = 0.f;
#pragma unroll
    for (int u = 0; u < 8; u++) { float d = a[u] - m; v += d * d; }
    v *= 0.125f;
    float r = rsqrtf(v + 1e-5f);
#pragma unroll
    for (int u = 0; u < 8; u++) a[u] = fmaxf((a[u] - m) * r * g[u] + b[u], 0.f);
}
__device__ __forceinline__ void fc8(const float* a, float* y, const float* w, const float* b) {
#pragma unroll
    for (int o = 0; o < 8; o++) {
        float s = b[o];
#pragma unroll
        for (int u = 0; u < 8; u++) s += a[u] * w[o * 8 + u];
        y[o] = s;
    }
}

__global__ void prep_pos_kernel(
    const float* __restrict__ pp_w, const float* __restrict__ pp_b,
    const float* __restrict__ l1_g, const float* __restrict__ l1_b,
    const float* __restrict__ f1_w, const float* __restrict__ f1_b,
    const float* __restrict__ l2_g, const float* __restrict__ l2_b,
    const float* __restrict__ f2_w, const float* __restrict__ f2_b,
    const float* __restrict__ l3_g, const float* __restrict__ l3_b,
    const float* __restrict__ f3_w, const float* __restrict__ f3_b)
{
    int p = blockIdx.x * blockDim.x + threadIdx.x;
    if (p >= POSN) return;
    float bh = (float)(p / 31 - 15);
    float bw = (float)(p % 31 - 15);
    float a[8], y[8];
#pragma unroll
    for (int u = 0; u < 8; u++) a[u] = bh * pp_w[2 * u] + bw * pp_w[2 * u + 1] + pp_b[u];
    ln_relu8(a, l1_g, l1_b);
    fc8(a, y, f1_w, f1_b);
    ln_relu8(y, l2_g, l2_b);
    fc8(y, a, f2_w, f2_b);
    ln_relu8(a, l3_g, l3_b);
#pragma unroll
    for (int hh = 0; hh < HEADS; hh++) {
        float s = f3_b[hh];
#pragma unroll
        for (int u = 0; u < 8; u++) s += a[u] * f3_w[hh * 8 + u];
        g_pos[hh * POSN + p] = s * LOG2E;
    }
}

// ---------------- fold LN gamma into W, bf16 ----------------
__global__ void prep_w_kernel(const float* __restrict__ qkv_w, const float* __restrict__ qkv_b,
                              const float* __restrict__ g1, const float* __restrict__ b1)
{
    __shared__ float s1[128], s2[128];
    int j = blockIdx.x;
    int k = threadIdx.x;
    float w = qkv_w[j * 128 + k];
    float wg = w * g1[k];
    __nv_bfloat16 wbh = __float2bfloat16(wg);
    g_wb[j * 128 + k] = *(unsigned short*)&wbh;
    s1[k] = __bfloat162float(wbh);
    s2[k] = w * b1[k];
    __syncthreads();
    for (int o = 64; o > 0; o >>= 1) {
        if (k < o) { s1[k] += s1[k + o]; s2[k] += s2[k + o]; }
        __syncthreads();
    }
    if (k == 0) {
        float cb = s2[0] + qkv_b[j];
        if (j < 128) cb *= QKSCALE * LOG2E;
        g_cs[j] = s1[0];
        g_cb[j] = cb;
    }
}

// ---------------- QKV GEMM (128 rows x 384 cols per CTA, 512 threads) ----------------
#define QX_XB   0                       // 128 rows x 272B
#define QX_WB   34816                   // 384 rows x 272B
#define QX_CS   139264
#define QX_CB   140800
#define QX_MEAN 142336
#define QX_RSTD 142848
#define QKV_SMEM 143360
// epilogue staging (reuses XB/WB region): 12 blocks x [128 n][80B] = 122880B

__global__ __launch_bounds__(512, 1) void qkv_kernel(const float* __restrict__ x)
{
    extern __shared__ char smc[];
    uint32_t sb = smem_u32(smc);
    float* scs   = (float*)(smc + QX_CS);
    float* scb   = (float*)(smc + QX_CB);
    float* smean = (float*)(smc + QX_MEAN);
    float* srstd = (float*)(smc + QX_RSTD);

    int tid = threadIdx.x;
    int wid = tid >> 5, lane = tid & 31;
    int t0 = blockIdx.x * 128;

    {
        const uint4* src = (const uint4*)g_wb;
#pragma unroll
        for (int i = 0; i < 12; i++) {
            int f = i * 512 + tid;
            int j = f >> 4, c = f & 15;
            *(uint4*)(smc + QX_WB + j * 272 + c * 16) = src[f];
        }
    }
    for (int p = tid; p < 384; p += 512) { scs[p] = g_cs[p]; scb[p] = g_cb[p]; }

    {
        int row = tid >> 2, qtr = tid & 3;
        int t = t0 + row;
        int w = t >> 8, n = t & 255;
        int imgrow = ((w >> 8) << 16) + (((((w >> 4) & 15) << 4) + (n >> 4)) << 8)
                   + ((w & 15) << 4) + (n & 15);
        const float4* src4 = (const float4*)(x + (size_t)imgrow * 128 + qtr * 32);
        float s = 0.f, q = 0.f;
#pragma unroll
        for (int i = 0; i < 4; i++) {
            float4 a = src4[2 * i], b = src4[2 * i + 1];
            s += a.x + a.y + a.z + a.w + b.x + b.y + b.z + b.w;
            q += a.x*a.x + a.y*a.y + a.z*a.z + a.w*a.w + b.x*b.x + b.y*b.y + b.z*b.z + b.w*b.w;
            uint4 o;
            o.x = bf2pack(a.x, a.y); o.y = bf2pack(a.z, a.w);
            o.z = bf2pack(b.x, b.y); o.w = bf2pack(b.z, b.w);
            *(uint4*)(smc + QX_XB + row * 272 + qtr * 64 + i * 16) = o;
        }
        s += __shfl_xor_sync(0xffffffffu, s, 1);
        q += __shfl_xor_sync(0xffffffffu, q, 1);
        s += __shfl_xor_sync(0xffffffffu, s, 2);
        q += __shfl_xor_sync(0xffffffffu, q, 2);
        if ((lane & 3) == 0) {
            float mu = s * (1.f / 128.f);
            smean[row] = mu;
            srstd[row] = rsqrtf(q * (1.f / 128.f) - mu * mu + 1e-5f);
        }
    }
    __syncthreads();

    int rg = wid >> 2, cg = wid & 3;

    float c[2][12][4];
#pragma unroll
    for (int t = 0; t < 2; t++)
#pragma unroll
        for (int nj = 0; nj < 12; nj++) {
            c[t][nj][0] = 0.f; c[t][nj][1] = 0.f; c[t][nj][2] = 0.f; c[t][nj][3] = 0.f;
        }

    for (int kk = 0; kk < 4; kk++) {
        uint32_t af[2][2][4];
#pragma unroll
        for (int t = 0; t < 2; t++)
#pragma unroll
            for (int ks = 0; ks < 2; ks++) {
                uint32_t addr = sb + QX_XB
                    + (rg * 32 + t * 16 + (lane & 7) + ((lane >> 3) & 1) * 8) * 272
                    + (kk * 32 + ks * 16 + (lane >> 4) * 8) * 2;
                ldmx4(af[t][ks], addr);
            }
#pragma unroll
        for (int nj = 0; nj < 12; nj++) {
            uint32_t bfr[4];
            uint32_t addr = sb + QX_WB + (cg * 96 + nj * 8 + (lane & 7)) * 272
                          + (kk * 32 + (lane >> 3) * 8) * 2;
            ldmx4(bfr, addr);
            mma16816(c[0][nj], af[0][0], &bfr[0]);
            mma16816(c[0][nj], af[0][1], &bfr[2]);
            mma16816(c[1][nj], af[1][0], &bfr[0]);
            mma16816(c[1][nj], af[1][1], &bfr[2]);
        }
    }

    float mn[2][2], rs[2][2];
#pragma unroll
    for (int t = 0; t < 2; t++) {
        int lr = rg * 32 + t * 16 + (lane >> 2);
        mn[t][0] = smean[lr];     mn[t][1] = smean[lr + 8];
        rs[t][0] = srstd[lr];     rs[t][1] = srstd[lr + 8];
    }

    // ---- epilogue: stage bf16 results in smem (reuse XB/WB, 80B stride), coalesced flush ----
    __syncthreads();   // all ldmatrix reads of XB/WB complete

#pragma unroll
    for (int nj = 0; nj < 12; nj++) {
        int j0 = cg * 96 + nj * 8 + 2 * (lane & 3);
        float2 cs2 = *(float2*)(scs + j0);
        float2 cb2 = *(float2*)(scb + j0);
        int blk = j0 >> 5;           // 0..11: kind*4 + head
        int d0 = j0 & 31;
        float qsc = (j0 < 128) ? (QKSCALE * LOG2E) : 1.f;
#pragma unroll
        for (int t = 0; t < 2; t++) {
            float ia = rs[t][0] * qsc, ib = rs[t][1] * qsc;
            float v00 = ia * (c[t][nj][0] - mn[t][0] * cs2.x) + cb2.x;
            float v01 = ia * (c[t][nj][1] - mn[t][0] * cs2.y) + cb2.y;
            float v10 = ib * (c[t][nj][2] - mn[t][1] * cs2.x) + cb2.x;
            float v11 = ib * (c[t][nj][3] - mn[t][1] * cs2.y) + cb2.y;
            int n = rg * 32 + t * 16 + (lane >> 2);
            *(uint32_t*)(smc + blk * 10240 + n * 80 + d0 * 2)       = bf2pack(v00, v01);
            *(uint32_t*)(smc + blk * 10240 + (n + 8) * 80 + d0 * 2) = bf2pack(v10, v11);
        }
    }
    __syncthreads();

    // coalesced flush: blk -> (kind, head); rows contiguous in g_q/g_k/g_v
    {
        int wv = blockIdx.x >> 1;
        int nof = (blockIdx.x & 1) * 128;
        int n = tid >> 2, cc = tid & 3;
#pragma unroll
        for (int blk = 0; blk < 12; blk++) {
            uint4 val = *(uint4*)(smc + blk * 10240 + n * 80 + cc * 16);
            int head = blk & 3, kind = blk >> 2;
            unsigned short* dst = (kind == 0) ? g_q : (kind == 1) ? g_k : g_v;
            *(uint4*)(dst + ((size_t)(wv * 4 + head) * 256 + nof + n) * 32 + cc * 8) = val;
        }
    }
}

// ---------------- attention: single-pass, 32 rows/warp, ldmatrix.trans V ----------------
#define AT_QS  0
#define AT_KS  20480
#define AT_VS  40960
#define AT_TAB 61440
#define ATTN_SMEM 69136

__global__ __launch_bounds__(256, 2) void attn_kernel(const float* __restrict__ x,
                                                      float* __restrict__ out)
{
    extern __shared__ char smc[];
    uint32_t sb = smem_u32(smc);
    float* tab = (float*)(smc + AT_TAB);
    int tid = threadIdx.x;
    int wid = tid >> 5, lane = tid & 31;
    int w = blockIdx.x >> 2, h = blockIdx.x & 3;
    size_t gbase = (size_t)(w * 4 + h) * (256 * 32);

    // paired pos table: tab[2t] = pos[t], tab[2t+1] = pos[t-1]
    for (int p = tid; p < POSN; p += 256) {
        float a = g_pos[h * POSN + p];
        tab[2 * p] = a;
        if (p < POSN - 1) tab[2 * p + 3] = a;
    }
    if (tid == 0) tab[1] = 0.f;

    // Qs/Ks/Vs: straight copy [256 tok][40 bf16]
    {
        const uint4* qsrc = (const uint4*)(g_q + gbase);
        const uint4* ksrc = (const uint4*)(g_k + gbase);
        const uint4* vsrc = (const uint4*)(g_v + gbase);
#pragma unroll
        for (int i = 0; i < 4; i++) {
            int c = i * 256 + tid;
            int n = c >> 2, ch = c & 3;
            *(uint4*)(smc + AT_QS + n * 80 + ch * 16) = qsrc[c];
            *(uint4*)(smc + AT_KS + n * 80 + ch * 16) = ksrc[c];
            *(uint4*)(smc + AT_VS + n * 80 + ch * 16) = vsrc[c];
        }
    }
    __syncthreads();

    int b_ = w >> 8, wh = (w >> 4) & 15, ww = w & 15;
    int r0 = wid * 32;
    int row0 = r0 + (lane >> 2);
    int tb0 = ((row0 >> 4) + 15) * 31 + (row0 & 15) + 15 - 2 * (lane & 3);

    // Q A-frags loaded once
    uint32_t af[2][2][4];
#pragma unroll
    for (int m = 0; m < 2; m++)
#pragma unroll
        for (int kt = 0; kt < 2; kt++) {
            uint32_t addr = sb + AT_QS
                + (r0 + m * 16 + (lane & 7) + ((lane >> 3) & 1) * 8) * 80
                + (kt * 16 + ((lane >> 3) >> 1) * 8) * 2;
            ldmx4(af[m][kt], addr);
        }

    float O[2][4][4];
#pragma unroll
    for (int m = 0; m < 2; m++)
#pragma unroll
        for (int nc2 = 0; nc2 < 4; nc2++) {
            O[m][nc2][0] = 0.f; O[m][nc2][1] = 0.f; O[m][nc2][2] = 0.f; O[m][nc2][3] = 0.f;
        }
    float sum00 = 0.f, sum01 = 0.f, sum10 = 0.f, sum11 = 0.f;

#pragma unroll
    for (int chunk = 0; chunk < 8; chunk++) {
        // ---- GEMM1 chunk ----
        float S[2][4][4];
#pragma unroll
        for (int nc = 0; nc < 4; nc++) {
            S[0][nc][0] = 0.f; S[0][nc][1] = 0.f; S[0][nc][2] = 0.f; S[0][nc][3] = 0.f;
            S[1][nc][0] = 0.f; S[1][nc][1] = 0.f; S[1][nc][2] = 0.f; S[1][nc][3] = 0.f;
            uint32_t bfr[4];
            uint32_t addr = sb + AT_KS
                + ((chunk * 4 + nc) * 8 + (lane & 7)) * 80 + (lane >> 3) * 16;
            ldmx4(bfr, addr);
            mma16816(S[0][nc], af[0][0], &bfr[0]);
            mma16816(S[0][nc], af[0][1], &bfr[2]);
            mma16816(S[1][nc], af[1][0], &bfr[0]);
            mma16816(S[1][nc], af[1][1], &bfr[2]);
        }

        // ---- bias + exp2 + pack ----
        uint32_t paA0[4], paB0[4], paA1[4], paB1[4];
#pragma unroll
        for (int nc = 0; nc < 4; nc++) {
            int g = chunk * 4 + nc;
            int t00 = tb0 - (g >> 1) * 31 - 8 * (g & 1);
            float2 b00 = *(const float2*)(tab + 2 * t00);
            float2 b08 = *(const float2*)(tab + 2 * t00 + 16);
            float2 b16 = *(const float2*)(tab + 2 * t00 + 62);
            float2 b24 = *(const float2*)(tab + 2 * t00 + 78);
            float e0 = ex2f(S[0][nc][0] + b00.x);
            float e1 = ex2f(S[0][nc][1] + b00.y);
            float e2 = ex2f(S[0][nc][2] + b08.x);
            float e3 = ex2f(S[0][nc][3] + b08.y);
            float f0 = ex2f(S[1][nc][0] + b16.x);
            float f1 = ex2f(S[1][nc][1] + b16.y);
            float f2 = ex2f(S[1][nc][2] + b24.x);
            float f3 = ex2f(S[1][nc][3] + b24.y);
            sum00 += e0 + e1; sum01 += e2 + e3;
            sum10 += f0 + f1; sum11 += f2 + f3;
            paA0[nc] = bf2pack(e0, e1);
            paB0[nc] = bf2pack(e2, e3);
            paA1[nc] = bf2pack(f0, f1);
            paB1[nc] = bf2pack(f2, f3);
        }

        // ---- partial GEMM2: V loaded via ldmatrix.trans from [tok][d] ----
        uint32_t a00[4] = {paA0[0], paB0[0], paA0[1], paB0[1]};
        uint32_t a01[4] = {paA0[2], paB0[2], paA0[3], paB0[3]};
        uint32_t a10[4] = {paA1[0], paB1[0], paA1[1], paB1[1]};
        uint32_t a11[4] = {paA1[2], paB1[2], paA1[3], paB1[3]};
#pragma unroll
        for (int dp = 0; dp < 2; dp++) {
            uint32_t T0[4], T1[4];
            uint32_t base = sb + AT_VS
                + (chunk * 32 + (lane & 7) + ((lane >> 3) & 1) * 8) * 80
                + (dp * 16 + ((lane >> 4) & 1) * 8) * 2;
            ldmx4t(T0, base);            // k0..15 of chunk
            ldmx4t(T1, base + 16 * 80);  // k16..31
            mma16816(O[0][dp * 2 + 0], a00, &T0[0]);
            mma16816(O[0][dp * 2 + 0], a01, &T1[0]);
            mma16816(O[0][dp * 2 + 1], a00, &T0[2]);
            mma16816(O[0][dp * 2 + 1], a01, &T1[2]);
            mma16816(O[1][dp * 2 + 0], a10, &T0[0]);
            mma16816(O[1][dp * 2 + 0], a11, &T1[0]);
            mma16816(O[1][dp * 2 + 1], a10, &T0[2]);
            mma16816(O[1][dp * 2 + 1], a11, &T1[2]);
        }
    }

    // ---- quad-reduce sums ----
    sum00 += __shfl_xor_sync(0xffffffffu, sum00, 1);
    sum00 += __shfl_xor_sync(0xffffffffu, sum00, 2);
    sum01 += __shfl_xor_sync(0xffffffffu, sum01, 1);
    sum01 += __shfl_xor_sync(0xffffffffu, sum01, 2);
    sum10 += __shfl_xor_sync(0xffffffffu, sum10, 1);
    sum10 += __shfl_xor_sync(0xffffffffu, sum10, 2);
    sum11 += __shfl_xor_sync(0xffffffffu, sum11, 1);
    sum11 += __shfl_xor_sync(0xffffffffu, sum11, 2);
    float inv[2][2];
    asm("rcp.approx.ftz.f32 %0,%1;" : "=f"(inv[0][0]) : "f"(sum00));
    asm("rcp.approx.ftz.f32 %0,%1;" : "=f"(inv[0][1]) : "f"(sum01));
    asm("rcp.approx.ftz.f32 %0,%1;" : "=f"(inv[1][0]) : "f"(sum10));
    asm("rcp.approx.ftz.f32 %0,%1;" : "=f"(inv[1][1]) : "f"(sum11));

    // ---- epilogue ----
#pragma unroll
    for (int m = 0; m < 2; m++) {
        int n0 = row0 + m * 16;
        int n1 = n0 + 8;
        int ir0 = (b_ << 16) + (((wh << 4) + (n0 >> 4)) << 8) + (ww << 4) + (n0 & 15);
        int ir1 = (b_ << 16) + (((wh << 4) + (n1 >> 4)) << 8) + (ww << 4) + (n1 & 15);
        const float* xr0 = x + (size_t)ir0 * 128 + h * 32;
        const float* xr1 = x + (size_t)ir1 * 128 + h * 32;
        float* or0 = out + (size_t)ir0 * 128 + h * 32;
        float* or1 = out + (size_t)ir1 * 128 + h * 32;
#pragma unroll
        for (int nc2 = 0; nc2 < 4; nc2++) {
            int d0 = nc2 * 8 + 2 * (lane & 3);
            float2 xv0 = *(const float2*)(xr0 + d0);
            float2 xv1 = *(const float2*)(xr1 + d0);
            float2 o0, o1;
            o0.x = O[m][nc2][0] * inv[m][0] + xv0.x;
            o0.y = O[m][nc2][1] * inv[m][0] + xv0.y;
            o1.x = O[m][nc2][2] * inv[m][1] + xv1.x;
            o1.y = O[m][nc2][3] * inv[m][1] + xv1.y;
            *(float2*)(or0 + d0) = o0;
            *(float2*)(or1 + d0) = o1;
        }
    }
}

// ---------------- launch ----------------
extern "C" void kernel_launch(void* const* d_in, const int* in_sizes, int n_in,
                              void* d_out, int out_size)
{
    (void)in_sizes; (void)n_in; (void)out_size;
    const float* x      = (const float*)d_in[0];
    const float* n1g    = (const float*)d_in[1];
    const float* n1b    = (const float*)d_in[2];
    const float* qkv_w  = (const float*)d_in[3];
    const float* qkv_b  = (const float*)d_in[4];
    const float* pp_w   = (const float*)d_in[5];
    const float* pp_b   = (const float*)d_in[6];
    const float* l1_g   = (const float*)d_in[7];
    const float* l1_b   = (const float*)d_in[8];
    const float* f1_w   = (const float*)d_in[9];
    const float* f1_b   = (const float*)d_in[10];
    const float* l2_g   = (const float*)d_in[11];
    const float* l2_b   = (const float*)d_in[12];
    const float* f2_w   = (const float*)d_in[13];
    const float* f2_b   = (const float*)d_in[14];
    const float* l3_g   = (const float*)d_in[15];
    const float* l3_b   = (const float*)d_in[16];
    const float* f3_w   = (const float*)d_in[17];
    const float* f3_b   = (const float*)d_in[18];
    float* out = (float*)d_out;

    cudaFuncSetAttribute(qkv_kernel,  cudaFuncAttributeMaxDynamicSharedMemorySize, QKV_SMEM);
    cudaFuncSetAttribute(attn_kernel, cudaFuncAttributeMaxDynamicSharedMemorySize, ATTN_SMEM);

    prep_pos_kernel<<<1, 1024>>>(pp_w, pp_b, l1_g, l1_b, f1_w, f1_b,
                                 l2_g, l2_b, f2_w, f2_b, l3_g, l3_b, f3_w, f3_b);
    prep_w_kernel<<<384, 128>>>(qkv_w, qkv_b, n1g, n1b);
    qkv_kernel<<<1024, 512, QKV_SMEM>>>(x);
    attn_kernel<<<2048, 256, ATTN_SMEM>>>(x, out);
}